// round 3
// baseline (speedup 1.0000x reference)
#include <cuda_runtime.h>
#include <cstdint>

// ---------------------------------------------------------------------------
// MSAttention: einsum 'bkhwlm,bkhwlnf->bkhwlf' factorizes as
// (sum_m A)*(sum_n V) = 1 * sum_n V  =>  attention is dead code. Output is a
// sum of V-projections of (block-sum) pooled inputs:
//   out0 (8,16,16,256) = Wvkid0*pool2(x1) + up4( Wvpeer0*pool4(x0) )
//   out1 (8,32,32,256) = Wvkid1*pool2(x2) + up2( Wvpeer1*pool2(x1) + Wvpar1*x0 )
//   out2 (8,64,64,256) =                    up2( Wvpeer2*pool2(x2) + Wvpar2*x1 )
// Wv* = rows [256,512) of the kv weights.
//
// 3 launches: pool3 -> coarse GEMMs (C0,C1 scratch + out2 scatter) ->
// fine GEMMs (out0,out1 with gathered coarse add).
// ---------------------------------------------------------------------------

__device__ float g_P0[8 * 4 * 4 * 256];     // pool4(x0)
__device__ float g_Pa[8 * 16 * 16 * 256];   // pool2(x1)
__device__ float g_Pb[8 * 32 * 32 * 256];   // pool2(x2)
__device__ float g_C0[128 * 256];           // P0 @ Wvpeer0^T
__device__ float g_C1[2048 * 256];          // Pa @ Wvpeer1^T + x0 @ Wvpar1^T

// ---------------------------------------------------------------------------
// Fused pooling: one launch for all three pools.
// ---------------------------------------------------------------------------
#define P0_N4 (8 * 4 * 4 * 64)
#define PA_N4 (8 * 16 * 16 * 64)
#define PB_N4 (8 * 32 * 32 * 64)

__global__ void pool3_kernel(const float* __restrict__ x0,
                             const float* __restrict__ x1,
                             const float* __restrict__ x2) {
    int i = blockIdx.x * blockDim.x + threadIdx.x;
    const float* in;
    float* out;
    int Hc, f;
    if (i < P0_N4) { in = x0; out = g_P0; Hc = 4; f = 4; }
    else if (i < P0_N4 + PA_N4) { i -= P0_N4; in = x1; out = g_Pa; Hc = 16; f = 2; }
    else if (i < P0_N4 + PA_N4 + PB_N4) { i -= P0_N4 + PA_N4; in = x2; out = g_Pb; Hc = 32; f = 2; }
    else return;
    int Wc = Hc;
    int c4 = i & 63;
    int r = i >> 6;
    int q = r % Wc; r /= Wc;
    int p = r % Hc;
    int b = r / Hc;
    int Win = Wc * f;
    const float4* in4 = (const float4*)in;
    float4 s = make_float4(0.f, 0.f, 0.f, 0.f);
    for (int dy = 0; dy < f; ++dy) {
        for (int dx = 0; dx < f; ++dx) {
            float4 v = in4[(size_t)((b * Hc * f + p * f + dy) * Win + q * f + dx) * 64 + c4];
            s.x += v.x; s.y += v.y; s.z += v.z; s.w += v.w;
        }
    }
    ((float4*)out)[i] = s;
}

// ---------------------------------------------------------------------------
// f32x2 helpers
// ---------------------------------------------------------------------------
__device__ __forceinline__ void fma2(unsigned long long& d, unsigned long long a,
                                     unsigned long long b) {
    asm("fma.rn.f32x2 %0, %1, %2, %0;" : "+l"(d) : "l"(a), "l"(b));
}
__device__ __forceinline__ float f2lo(unsigned long long v) {
    return __uint_as_float((unsigned int)(v & 0xffffffffull));
}
__device__ __forceinline__ float f2hi(unsigned long long v) {
    return __uint_as_float((unsigned int)(v >> 32));
}

// ---------------------------------------------------------------------------
// Multi-job GEMM. out[m,n] = sum_k A1[m,k]W1[n,k] (+ A2[m,k]W2[n,k]).
// BM=128, BN=64, BK=16, 256 threads, double-buffered smem, one sync/tile.
// B stored DUPLICATED in smem so the f32x2 broadcast operand is a direct
// LDS.128 (no mov.b64 dup in the inner loop).
// mode 0: store at row m (scratch)
// mode 1: scatter-write, nearest-neighbor upsample by F from coarse (Hc,Wc)
// mode 2: store at fine row m, adding gathered Cadd[coarse(m)]
// ---------------------------------------------------------------------------
struct Job {
    const float* A1; const float* W1;
    const float* A2; const float* W2;
    float* out;
    const float* Cadd;
    int tile_end;   // cumulative (tiles = mtiles*4)
    int Hc, Wc, F, mode;
};
struct Jobs { Job j[3]; int njobs; };

__global__ void __launch_bounds__(256, 2)
gemm_fused(Jobs jobs) {
    __shared__ float As[2][16][128];
    __shared__ float Bs[2][16][128];   // duplicated: Bs[k][2n]=Bs[k][2n+1]=B[n,k]

    const int bt = blockIdx.x;
    int ji = 0;
    if (jobs.njobs > 1 && bt >= jobs.j[0].tile_end) ji = 1;
    if (jobs.njobs > 2 && bt >= jobs.j[1].tile_end) ji = 2;
    const Job jb = jobs.j[ji];
    const int local = bt - (ji == 0 ? 0 : jobs.j[ji - 1].tile_end);
    const int m0 = (local >> 2) * 128;
    const int n0 = (local & 3) * 64;

    const int t = threadIdx.x;
    const int tn = t & 15;
    const int tm = t >> 4;
    const int ar = t >> 2;         // 0..63
    const int ak = (t & 3) << 2;   // 0,4,8,12

    const int KT = jb.A2 ? 32 : 16;

    unsigned long long acc[4][4];
#pragma unroll
    for (int p = 0; p < 4; ++p)
#pragma unroll
        for (int j = 0; j < 4; ++j) acc[p][j] = 0ull;

    // Prologue: tile 0 -> buf 0
    {
        float4 av0 = *(const float4*)&jb.A1[(size_t)(m0 + ar) * 256 + ak];
        float4 av1 = *(const float4*)&jb.A1[(size_t)(m0 + ar + 64) * 256 + ak];
        float4 bv  = *(const float4*)&jb.W1[(size_t)(n0 + ar) * 256 + ak];
        As[0][ak + 0][ar] = av0.x; As[0][ak + 1][ar] = av0.y;
        As[0][ak + 2][ar] = av0.z; As[0][ak + 3][ar] = av0.w;
        As[0][ak + 0][ar + 64] = av1.x; As[0][ak + 1][ar + 64] = av1.y;
        As[0][ak + 2][ar + 64] = av1.z; As[0][ak + 3][ar + 64] = av1.w;
        *(float2*)&Bs[0][ak + 0][ar * 2] = make_float2(bv.x, bv.x);
        *(float2*)&Bs[0][ak + 1][ar * 2] = make_float2(bv.y, bv.y);
        *(float2*)&Bs[0][ak + 2][ar * 2] = make_float2(bv.z, bv.z);
        *(float2*)&Bs[0][ak + 3][ar * 2] = make_float2(bv.w, bv.w);
    }
    __syncthreads();

#pragma unroll 1
    for (int kt = 0; kt < KT; ++kt) {
        const int cb = kt & 1;
        float4 nav0, nav1, nbv;
        const bool more = (kt + 1 < KT);
        if (more) {
            const float* A = (kt + 1 < 16) ? jb.A1 : jb.A2;
            const float* W = (kt + 1 < 16) ? jb.W1 : jb.W2;
            const int k0 = ((kt + 1) & 15) * 16;
            nav0 = *(const float4*)&A[(size_t)(m0 + ar) * 256 + k0 + ak];
            nav1 = *(const float4*)&A[(size_t)(m0 + ar + 64) * 256 + k0 + ak];
            nbv  = *(const float4*)&W[(size_t)(n0 + ar) * 256 + k0 + ak];
        }
#pragma unroll
        for (int k = 0; k < 16; ++k) {
            ulonglong2 a01 = *(const ulonglong2*)&As[cb][k][tm * 8];
            ulonglong2 a23 = *(const ulonglong2*)&As[cb][k][tm * 8 + 4];
            ulonglong2 b01 = *(const ulonglong2*)&Bs[cb][k][tn * 8];
            ulonglong2 b23 = *(const ulonglong2*)&Bs[cb][k][tn * 8 + 4];
            fma2(acc[0][0], a01.x, b01.x); fma2(acc[0][1], a01.x, b01.y);
            fma2(acc[0][2], a01.x, b23.x); fma2(acc[0][3], a01.x, b23.y);
            fma2(acc[1][0], a01.y, b01.x); fma2(acc[1][1], a01.y, b01.y);
            fma2(acc[1][2], a01.y, b23.x); fma2(acc[1][3], a01.y, b23.y);
            fma2(acc[2][0], a23.x, b01.x); fma2(acc[2][1], a23.x, b01.y);
            fma2(acc[2][2], a23.x, b23.x); fma2(acc[2][3], a23.x, b23.y);
            fma2(acc[3][0], a23.y, b01.x); fma2(acc[3][1], a23.y, b01.y);
            fma2(acc[3][2], a23.y, b23.x); fma2(acc[3][3], a23.y, b23.y);
        }
        if (more) {
            const int nb = cb ^ 1;
            As[nb][ak + 0][ar] = nav0.x; As[nb][ak + 1][ar] = nav0.y;
            As[nb][ak + 2][ar] = nav0.z; As[nb][ak + 3][ar] = nav0.w;
            As[nb][ak + 0][ar + 64] = nav1.x; As[nb][ak + 1][ar + 64] = nav1.y;
            As[nb][ak + 2][ar + 64] = nav1.z; As[nb][ak + 3][ar + 64] = nav1.w;
            *(float2*)&Bs[nb][ak + 0][ar * 2] = make_float2(nbv.x, nbv.x);
            *(float2*)&Bs[nb][ak + 1][ar * 2] = make_float2(nbv.y, nbv.y);
            *(float2*)&Bs[nb][ak + 2][ar * 2] = make_float2(nbv.z, nbv.z);
            *(float2*)&Bs[nb][ak + 3][ar * 2] = make_float2(nbv.w, nbv.w);
        }
        __syncthreads();
    }

    // Epilogue
    const int nbase = n0 + tn * 4;
#pragma unroll
    for (int i = 0; i < 8; ++i) {
        const int p = i >> 1;
        float4 v;
        if ((i & 1) == 0)
            v = make_float4(f2lo(acc[p][0]), f2lo(acc[p][1]), f2lo(acc[p][2]), f2lo(acc[p][3]));
        else
            v = make_float4(f2hi(acc[p][0]), f2hi(acc[p][1]), f2hi(acc[p][2]), f2hi(acc[p][3]));
        const int m = m0 + tm * 8 + i;

        if (jb.mode == 0) {
            *(float4*)&jb.out[(size_t)m * 256 + nbase] = v;
        } else if (jb.mode == 1) {
            // m is a coarse row; scatter-write FxF fine positions
            const int HW = jb.Hc * jb.Wc;
            const int b = m / HW;
            const int rem = m - b * HW;
            const int h = rem / jb.Wc;
            const int w = rem - h * jb.Wc;
            const int Wf = jb.Wc * jb.F;
            for (int dy = 0; dy < jb.F; ++dy)
                for (int dx = 0; dx < jb.F; ++dx) {
                    size_t fm = (size_t)(b * jb.Hc * jb.F + h * jb.F + dy) * Wf + (w * jb.F + dx);
                    *(float4*)&jb.out[fm * 256 + nbase] = v;
                }
        } else {
            // m is a fine row; gather coarse contribution and add
            const int Hf = jb.Hc * jb.F, Wf = jb.Wc * jb.F;
            const int HWf = Hf * Wf;
            const int b = m / HWf;
            const int rem = m - b * HWf;
            const int h = rem / Wf;
            const int w = rem - h * Wf;
            const int crow = (b * jb.Hc + h / jb.F) * jb.Wc + (w / jb.F);
            float4 c = *(const float4*)&jb.Cadd[(size_t)crow * 256 + nbase];
            v.x += c.x; v.y += c.y; v.z += c.z; v.w += c.w;
            *(float4*)&jb.out[(size_t)m * 256 + nbase] = v;
        }
    }
}

// ---------------------------------------------------------------------------
// Launch
// ---------------------------------------------------------------------------
extern "C" void kernel_launch(void* const* d_in, const int* in_sizes, int n_in,
                              void* d_out, int out_size) {
    (void)n_in; (void)out_size;

    const float* x0 = (const float*)d_in[0];   // [8,16,16,256]
    const float* x1 = (const float*)d_in[1];   // [8,32,32,256]
    const float* x2 = (const float*)d_in[2];   // [8,64,64,256]

    // setup_inputs() builds the dict INTERLEAVED (qpeer_w0, kvpeer_w0, ...).
    // Disambiguate by element count: kv = 512*256, q = 256*256.
    const bool inter = (in_sizes[4] == 2 * 256 * 256);
    const float* kvpeer0 = (const float*)d_in[inter ? 4  : 6];
    const float* kvpeer1 = (const float*)d_in[inter ? 6  : 7];
    const float* kvpeer2 = (const float*)d_in[inter ? 8  : 8];
    const float* kvpar1  = (const float*)d_in[inter ? 10 : 11];
    const float* kvpar2  = (const float*)d_in[inter ? 12 : 12];
    const float* kvkid0  = (const float*)d_in[inter ? 14 : 15];
    const float* kvkid1  = (const float*)d_in[inter ? 16 : 16];
    const int VOFF = 256 * 256;  // V half = rows [256,512)

    float *P0, *Pa, *Pb, *C0, *C1;
    cudaGetSymbolAddress((void**)&P0, g_P0);
    cudaGetSymbolAddress((void**)&Pa, g_Pa);
    cudaGetSymbolAddress((void**)&Pb, g_Pb);
    cudaGetSymbolAddress((void**)&C0, g_C0);
    cudaGetSymbolAddress((void**)&C1, g_C1);

    float* out0 = (float*)d_out;                 // 8*16*16*256
    float* out1 = out0 + 8 * 16 * 16 * 256;      // 8*32*32*256
    float* out2 = out1 + 8 * 32 * 32 * 256;      // 8*64*64*256

    // 1) pools
    const int poolN = P0_N4 + PA_N4 + PB_N4;
    pool3_kernel<<<(poolN + 255) / 256, 256>>>(x0, x1, x2);

    // 2) coarse GEMMs: C0, C1 scratch; out2 scatter-written directly
    Jobs cj;
    cj.njobs = 3;
    cj.j[0] = { P0, kvpeer0 + VOFF, nullptr, nullptr, C0,   nullptr, 4,   0,  0,  0, 0 };
    cj.j[1] = { Pa, kvpeer1 + VOFF, x0, kvpar1 + VOFF, C1,   nullptr, 68,  0,  0,  0, 0 };
    cj.j[2] = { Pb, kvpeer2 + VOFF, x1, kvpar2 + VOFF, out2, nullptr, 324, 32, 32, 2, 1 };
    gemm_fused<<<324, 256>>>(cj);

    // 3) fine GEMMs with gathered coarse add
    Jobs fj;
    fj.njobs = 2;
    fj.j[0] = { Pa, kvkid0 + VOFF, nullptr, nullptr, out0, C0, 64,  4,  4,  4, 2 };
    fj.j[1] = { Pb, kvkid1 + VOFF, nullptr, nullptr, out1, C1, 320, 16, 16, 2, 2 };
    fj.j[2] = fj.j[1];
    gemm_fused<<<320, 256>>>(fj);
}

// round 4
// speedup vs baseline: 1.4091x; 1.4091x over previous
#include <cuda_runtime.h>
#include <cstdint>

// ---------------------------------------------------------------------------
// MSAttention: einsum 'bkhwlm,bkhwlnf->bkhwlf' factorizes as
// (sum_m A)*(sum_n V) = 1 * sum_n V  =>  attention is dead code. Output is a
// sum of V-projections of (block-sum) pooled inputs:
//   out0 (8,16,16,256) = Wvkid0*pool2(x1) + up4( Wvpeer0*pool4(x0) )
//   out1 (8,32,32,256) = Wvkid1*pool2(x2) + up2( Wvpeer1*pool2(x1) + Wvpar1*x0 )
//   out2 (8,64,64,256) =                    up2( Wvpeer2*pool2(x2) + Wvpar2*x1 )
// Wv* = rows [256,512) of the kv weights.
// ---------------------------------------------------------------------------

__device__ float g_P0[8 * 4 * 4 * 256];     // pool4(x0)
__device__ float g_Pa[8 * 16 * 16 * 256];   // pool2(x1)
__device__ float g_Pb[8 * 32 * 32 * 256];   // pool2(x2)
__device__ float g_C0[128 * 256];           // P0 @ Wvpeer0^T
__device__ float g_C1[2048 * 256];          // Pa @ Wvpeer1^T + x0 @ Wvpar1^T

// ---------------------------------------------------------------------------
// Fused pooling
// ---------------------------------------------------------------------------
#define P0_N4 (8 * 4 * 4 * 64)
#define PA_N4 (8 * 16 * 16 * 64)
#define PB_N4 (8 * 32 * 32 * 64)

__global__ void pool3_kernel(const float* __restrict__ x0,
                             const float* __restrict__ x1,
                             const float* __restrict__ x2) {
    int i = blockIdx.x * blockDim.x + threadIdx.x;
    const float* in;
    float* out;
    int Hc, f;
    if (i < P0_N4) { in = x0; out = g_P0; Hc = 4; f = 4; }
    else if (i < P0_N4 + PA_N4) { i -= P0_N4; in = x1; out = g_Pa; Hc = 16; f = 2; }
    else if (i < P0_N4 + PA_N4 + PB_N4) { i -= P0_N4 + PA_N4; in = x2; out = g_Pb; Hc = 32; f = 2; }
    else return;
    int Wc = Hc;
    int c4 = i & 63;
    int r = i >> 6;
    int q = r % Wc; r /= Wc;
    int p = r % Hc;
    int b = r / Hc;
    int Win = Wc * f;
    const float4* in4 = (const float4*)in;
    float4 s = make_float4(0.f, 0.f, 0.f, 0.f);
    for (int dy = 0; dy < f; ++dy) {
        for (int dx = 0; dx < f; ++dx) {
            float4 v = in4[(size_t)((b * Hc * f + p * f + dy) * Win + q * f + dx) * 64 + c4];
            s.x += v.x; s.y += v.y; s.z += v.z; s.w += v.w;
        }
    }
    ((float4*)out)[i] = s;
}

// ---------------------------------------------------------------------------
// f32x2 helpers
// ---------------------------------------------------------------------------
__device__ __forceinline__ unsigned long long dupf(float x) {
    unsigned long long r;
    unsigned int u = __float_as_uint(x);
    asm("mov.b64 %0, {%1, %1};" : "=l"(r) : "r"(u));
    return r;
}
__device__ __forceinline__ void fma2(unsigned long long& d, unsigned long long a,
                                     unsigned long long b) {
    asm("fma.rn.f32x2 %0, %1, %2, %0;" : "+l"(d) : "l"(a), "l"(b));
}
__device__ __forceinline__ float f2lo(unsigned long long v) {
    return __uint_as_float((unsigned int)(v & 0xffffffffull));
}
__device__ __forceinline__ float f2hi(unsigned long long v) {
    return __uint_as_float((unsigned int)(v >> 32));
}

// ---------------------------------------------------------------------------
// Multi-job GEMM. out[m,n] = sum_k A1[m,k]W1[n,k] (+ A2[m,k]W2[n,k]).
// BM=128, BN=128, BK=16, 256 threads, 8x8 microtile split as two 4-quads
// ({4t..4t+3} and {64+4t..64+4t+3}) so all LDS.128 are 16B-lane-stride
// (conflict-free). Double-buffered smem, one sync per k-tile.
// mode 0: store at row m (scratch)
// mode 1: scatter-write, nearest-neighbor upsample by F from coarse (Hc,Wc)
// mode 2: store at fine row m, adding gathered Cadd[coarse(m)]
// ---------------------------------------------------------------------------
struct Job {
    const float* A1; const float* W1;
    const float* A2; const float* W2;
    float* out;
    const float* Cadd;
    int tile_end;   // cumulative; tiles per job = mtiles*2 (N=256 -> 2 n-tiles)
    int Hc, Wc, F, mode;
};
struct Jobs { Job j[3]; int njobs; };

__device__ __forceinline__ void store_out(const Job& jb, int m, int n, float4 v) {
    if (jb.mode == 0) {
        *(float4*)&jb.out[(size_t)m * 256 + n] = v;
    } else if (jb.mode == 1) {
        const int HW = jb.Hc * jb.Wc;
        const int b = m / HW;
        const int rem = m - b * HW;
        const int h = rem / jb.Wc;
        const int w = rem - h * jb.Wc;
        const int Wf = jb.Wc * jb.F;
        for (int dy = 0; dy < jb.F; ++dy)
            for (int dx = 0; dx < jb.F; ++dx) {
                size_t fm = (size_t)(b * jb.Hc * jb.F + h * jb.F + dy) * Wf + (w * jb.F + dx);
                *(float4*)&jb.out[fm * 256 + n] = v;
            }
    } else {
        const int Wf = jb.Wc * jb.F;
        const int HWf = jb.Hc * jb.F * Wf;
        const int b = m / HWf;
        const int rem = m - b * HWf;
        const int h = rem / Wf;
        const int w = rem - h * Wf;
        const int crow = (b * jb.Hc + h / jb.F) * jb.Wc + (w / jb.F);
        float4 c = *(const float4*)&jb.Cadd[(size_t)crow * 256 + n];
        v.x += c.x; v.y += c.y; v.z += c.z; v.w += c.w;
        *(float4*)&jb.out[(size_t)m * 256 + n] = v;
    }
}

__global__ void __launch_bounds__(256, 2)
gemm_fused(Jobs jobs) {
    __shared__ float As[2][16][128];
    __shared__ float Bs[2][16][128];

    const int bt = blockIdx.x;
    int ji = 0;
    if (jobs.njobs > 1 && bt >= jobs.j[0].tile_end) ji = 1;
    if (jobs.njobs > 2 && bt >= jobs.j[1].tile_end) ji = 2;
    const Job jb = jobs.j[ji];
    const int local = bt - (ji == 0 ? 0 : jobs.j[ji - 1].tile_end);
    const int m0 = (local >> 1) * 128;
    const int n0 = (local & 1) * 128;

    const int t = threadIdx.x;
    const int tn = t & 15;
    const int tm = t >> 4;
    const int lr = t >> 2;         // 0..63
    const int lc = (t & 3) << 2;   // 0,4,8,12

    const int KT = jb.A2 ? 32 : 16;

    // acc[mh][p][nh][j]: mh,nh = quad halves; p = m-pair in quad; j = n in quad
    unsigned long long acc[2][2][2][4];
#pragma unroll
    for (int a = 0; a < 2; ++a)
#pragma unroll
        for (int p = 0; p < 2; ++p)
#pragma unroll
            for (int c = 0; c < 2; ++c)
#pragma unroll
                for (int j = 0; j < 4; ++j) acc[a][p][c][j] = 0ull;

    // Prologue: tile 0 -> buf 0
    {
        float4 av0 = *(const float4*)&jb.A1[(size_t)(m0 + lr) * 256 + lc];
        float4 av1 = *(const float4*)&jb.A1[(size_t)(m0 + lr + 64) * 256 + lc];
        float4 bv0 = *(const float4*)&jb.W1[(size_t)(n0 + lr) * 256 + lc];
        float4 bv1 = *(const float4*)&jb.W1[(size_t)(n0 + lr + 64) * 256 + lc];
        As[0][lc + 0][lr] = av0.x; As[0][lc + 1][lr] = av0.y;
        As[0][lc + 2][lr] = av0.z; As[0][lc + 3][lr] = av0.w;
        As[0][lc + 0][lr + 64] = av1.x; As[0][lc + 1][lr + 64] = av1.y;
        As[0][lc + 2][lr + 64] = av1.z; As[0][lc + 3][lr + 64] = av1.w;
        Bs[0][lc + 0][lr] = bv0.x; Bs[0][lc + 1][lr] = bv0.y;
        Bs[0][lc + 2][lr] = bv0.z; Bs[0][lc + 3][lr] = bv0.w;
        Bs[0][lc + 0][lr + 64] = bv1.x; Bs[0][lc + 1][lr + 64] = bv1.y;
        Bs[0][lc + 2][lr + 64] = bv1.z; Bs[0][lc + 3][lr + 64] = bv1.w;
    }
    __syncthreads();

#pragma unroll 1
    for (int kt = 0; kt < KT; ++kt) {
        const int cb = kt & 1;
        float4 nav0, nav1, nbv0, nbv1;
        const bool more = (kt + 1 < KT);
        if (more) {
            const float* A = (kt + 1 < 16) ? jb.A1 : jb.A2;
            const float* W = (kt + 1 < 16) ? jb.W1 : jb.W2;
            const int k0 = ((kt + 1) & 15) * 16;
            nav0 = *(const float4*)&A[(size_t)(m0 + lr) * 256 + k0 + lc];
            nav1 = *(const float4*)&A[(size_t)(m0 + lr + 64) * 256 + k0 + lc];
            nbv0 = *(const float4*)&W[(size_t)(n0 + lr) * 256 + k0 + lc];
            nbv1 = *(const float4*)&W[(size_t)(n0 + lr + 64) * 256 + k0 + lc];
        }
#pragma unroll
        for (int k = 0; k < 16; ++k) {
            ulonglong2 a0 = *(const ulonglong2*)&As[cb][k][tm * 4];
            ulonglong2 a1 = *(const ulonglong2*)&As[cb][k][64 + tm * 4];
            float4 bf0 = *(const float4*)&Bs[cb][k][tn * 4];
            float4 bf1 = *(const float4*)&Bs[cb][k][64 + tn * 4];
            unsigned long long b[8];
            b[0] = dupf(bf0.x); b[1] = dupf(bf0.y); b[2] = dupf(bf0.z); b[3] = dupf(bf0.w);
            b[4] = dupf(bf1.x); b[5] = dupf(bf1.y); b[6] = dupf(bf1.z); b[7] = dupf(bf1.w);
#pragma unroll
            for (int j = 0; j < 4; ++j) {
                fma2(acc[0][0][0][j], a0.x, b[j]);
                fma2(acc[0][1][0][j], a0.y, b[j]);
                fma2(acc[1][0][0][j], a1.x, b[j]);
                fma2(acc[1][1][0][j], a1.y, b[j]);
                fma2(acc[0][0][1][j], a0.x, b[4 + j]);
                fma2(acc[0][1][1][j], a0.y, b[4 + j]);
                fma2(acc[1][0][1][j], a1.x, b[4 + j]);
                fma2(acc[1][1][1][j], a1.y, b[4 + j]);
            }
        }
        if (more) {
            const int nb = cb ^ 1;
            As[nb][lc + 0][lr] = nav0.x; As[nb][lc + 1][lr] = nav0.y;
            As[nb][lc + 2][lr] = nav0.z; As[nb][lc + 3][lr] = nav0.w;
            As[nb][lc + 0][lr + 64] = nav1.x; As[nb][lc + 1][lr + 64] = nav1.y;
            As[nb][lc + 2][lr + 64] = nav1.z; As[nb][lc + 3][lr + 64] = nav1.w;
            Bs[nb][lc + 0][lr] = nbv0.x; Bs[nb][lc + 1][lr] = nbv0.y;
            Bs[nb][lc + 2][lr] = nbv0.z; Bs[nb][lc + 3][lr] = nbv0.w;
            Bs[nb][lc + 0][lr + 64] = nbv1.x; Bs[nb][lc + 1][lr + 64] = nbv1.y;
            Bs[nb][lc + 2][lr + 64] = nbv1.z; Bs[nb][lc + 3][lr + 64] = nbv1.w;
        }
        __syncthreads();
    }

    // Epilogue: thread owns m in {m0+4tm+i, m0+64+4tm+i}, n in {n0+4tn.., n0+64+4tn..}
#pragma unroll
    for (int mh = 0; mh < 2; ++mh) {
#pragma unroll
        for (int i = 0; i < 4; ++i) {
            const int p = i >> 1;
            const int m = m0 + mh * 64 + tm * 4 + i;
#pragma unroll
            for (int nh = 0; nh < 2; ++nh) {
                float4 v;
                if ((i & 1) == 0)
                    v = make_float4(f2lo(acc[mh][p][nh][0]), f2lo(acc[mh][p][nh][1]),
                                    f2lo(acc[mh][p][nh][2]), f2lo(acc[mh][p][nh][3]));
                else
                    v = make_float4(f2hi(acc[mh][p][nh][0]), f2hi(acc[mh][p][nh][1]),
                                    f2hi(acc[mh][p][nh][2]), f2hi(acc[mh][p][nh][3]));
                store_out(jb, m, n0 + nh * 64 + tn * 4, v);
            }
        }
    }
}

// ---------------------------------------------------------------------------
// Launch
// ---------------------------------------------------------------------------
extern "C" void kernel_launch(void* const* d_in, const int* in_sizes, int n_in,
                              void* d_out, int out_size) {
    (void)n_in; (void)out_size;

    const float* x0 = (const float*)d_in[0];   // [8,16,16,256]
    const float* x1 = (const float*)d_in[1];   // [8,32,32,256]
    const float* x2 = (const float*)d_in[2];   // [8,64,64,256]

    // setup_inputs() builds the dict INTERLEAVED (qpeer_w0, kvpeer_w0, ...).
    // Disambiguate by element count: kv = 512*256, q = 256*256.
    const bool inter = (in_sizes[4] == 2 * 256 * 256);
    const float* kvpeer0 = (const float*)d_in[inter ? 4  : 6];
    const float* kvpeer1 = (const float*)d_in[inter ? 6  : 7];
    const float* kvpeer2 = (const float*)d_in[inter ? 8  : 8];
    const float* kvpar1  = (const float*)d_in[inter ? 10 : 11];
    const float* kvpar2  = (const float*)d_in[inter ? 12 : 12];
    const float* kvkid0  = (const float*)d_in[inter ? 14 : 15];
    const float* kvkid1  = (const float*)d_in[inter ? 16 : 16];
    const int VOFF = 256 * 256;  // V half = rows [256,512)

    float *P0, *Pa, *Pb, *C0, *C1;
    cudaGetSymbolAddress((void**)&P0, g_P0);
    cudaGetSymbolAddress((void**)&Pa, g_Pa);
    cudaGetSymbolAddress((void**)&Pb, g_Pb);
    cudaGetSymbolAddress((void**)&C0, g_C0);
    cudaGetSymbolAddress((void**)&C1, g_C1);

    float* out0 = (float*)d_out;                 // 8*16*16*256
    float* out1 = out0 + 8 * 16 * 16 * 256;      // 8*32*32*256
    float* out2 = out1 + 8 * 32 * 32 * 256;      // 8*64*64*256

    // 1) pools
    const int poolN = P0_N4 + PA_N4 + PB_N4;
    pool3_kernel<<<(poolN + 255) / 256, 256>>>(x0, x1, x2);

    // 2) coarse GEMMs: C0, C1 scratch; out2 scatter-written directly
    Jobs cj;
    cj.njobs = 3;
    cj.j[0] = { P0, kvpeer0 + VOFF, nullptr, nullptr, C0,   nullptr, 2,   0,  0,  0, 0 };
    cj.j[1] = { Pa, kvpeer1 + VOFF, x0, kvpar1 + VOFF, C1,   nullptr, 34,  0,  0,  0, 0 };
    cj.j[2] = { Pb, kvpeer2 + VOFF, x1, kvpar2 + VOFF, out2, nullptr, 162, 32, 32, 2, 1 };
    gemm_fused<<<162, 256>>>(cj);

    // 3) fine GEMMs with gathered coarse add
    Jobs fj;
    fj.njobs = 2;
    fj.j[0] = { Pa, kvkid0 + VOFF, nullptr, nullptr, out0, C0, 32,  4,  4,  4, 2 };
    fj.j[1] = { Pb, kvkid1 + VOFF, nullptr, nullptr, out1, C1, 160, 16, 16, 2, 2 };
    fj.j[2] = fj.j[1];
    gemm_fused<<<160, 256>>>(fj);
}

// round 6
// speedup vs baseline: 2.6675x; 1.8931x over previous
#include <cuda_runtime.h>
#include <cuda_bf16.h>
#include <cstdint>

// ---------------------------------------------------------------------------
// MSAttention: einsum 'bkhwlm,bkhwlnf->bkhwlf' factorizes as
// (sum_m A)*(sum_n V) = 1 * sum_n V  =>  attention is dead code. Output is a
// sum of V-projections of (block-sum) pooled inputs:
//   out0 = Wvkid0*pool2(x1) + up4( Wvpeer0*pool4(x0) )
//   out1 = Wvkid1*pool2(x2) + up2( Wvpeer1*pool2(x1) + Wvpar1*x0 )
//   out2 =                    up2( Wvpeer2*pool2(x2) + Wvpar2*x1 )
// Wv* = rows [256,512) of the kv weights.
//
// GEMMs on tensor cores via mma.sync m16n8k16 bf16 (baseline PTX — the
// harness's ptxas target is sm_103 WITHOUT the 'a' suffix, so tcgen05 is
// unavailable). Split precision: D += Ah*Bh + Ah*Bl + Al*Bh, fp32 accum.
// ---------------------------------------------------------------------------

// ---- scratch (bf16 hi/lo operand copies) ----
__device__ __nv_bfloat16 g_P0h[128 * 256],  g_P0l[128 * 256];
__device__ __nv_bfloat16 g_Pah[2048 * 256], g_Pal[2048 * 256];
__device__ __nv_bfloat16 g_Pbh[8192 * 256], g_Pbl[8192 * 256];
__device__ __nv_bfloat16 g_X0h[2048 * 256], g_X0l[2048 * 256];
__device__ __nv_bfloat16 g_X1h[8192 * 256], g_X1l[8192 * 256];
__device__ __nv_bfloat16 g_Wh[7 * 65536],   g_Wl[7 * 65536];
__device__ float g_C0[128 * 256];
__device__ float g_C1[2048 * 256];

// ---------------------------------------------------------------------------
// PTX helpers (all baseline features: sm_80-era)
// ---------------------------------------------------------------------------
__device__ __forceinline__ uint32_t smem_to_u32(const void* p) {
    uint32_t a;
    asm("{ .reg .u64 t; cvta.to.shared.u64 t, %1; cvt.u32.u64 %0, t; }" : "=r"(a) : "l"(p));
    return a;
}
__device__ __forceinline__ void cp16(uint32_t smem, const void* gmem) {
    asm volatile("cp.async.cg.shared.global [%0], [%1], 16;" :: "r"(smem), "l"(gmem));
}
__device__ __forceinline__ void cp_commit() {
    asm volatile("cp.async.commit_group;" ::: "memory");
}
template <int N>
__device__ __forceinline__ void cp_wait() {
    asm volatile("cp.async.wait_group %0;" :: "n"(N) : "memory");
}
__device__ __forceinline__ void ldsm4(uint32_t* r, uint32_t addr) {
    asm volatile("ldmatrix.sync.aligned.m8n8.x4.shared.b16 {%0,%1,%2,%3}, [%4];"
                 : "=r"(r[0]), "=r"(r[1]), "=r"(r[2]), "=r"(r[3]) : "r"(addr));
}
__device__ __forceinline__ void ldsm2(uint32_t* r, uint32_t addr) {
    asm volatile("ldmatrix.sync.aligned.m8n8.x2.shared.b16 {%0,%1}, [%2];"
                 : "=r"(r[0]), "=r"(r[1]) : "r"(addr));
}
__device__ __forceinline__ void mma16816(float* d, const uint32_t* a, const uint32_t* b) {
    asm volatile(
        "mma.sync.aligned.m16n8k16.row.col.f32.bf16.bf16.f32 "
        "{%0,%1,%2,%3}, {%4,%5,%6,%7}, {%8,%9}, {%0,%1,%2,%3};"
        : "+f"(d[0]), "+f"(d[1]), "+f"(d[2]), "+f"(d[3])
        : "r"(a[0]), "r"(a[1]), "r"(a[2]), "r"(a[3]), "r"(b[0]), "r"(b[1]));
}

// ---------------------------------------------------------------------------
// Prep kernel: pools + fp32->bf16 hi/lo splits (A operands and V-weights).
// ---------------------------------------------------------------------------
#define S0 8192        // P0 pool  (f=4 from x0)
#define S1 131072      // Pa pool  (f=2 from x1)
#define S2 524288      // Pb pool  (f=2 from x2)
#define S3 131072      // X0 copy
#define S4 524288      // X1 copy
#define S5 114688      // weights 7 * 65536 / 4
#define PREP_TOTAL (S0 + S1 + S2 + S3 + S4 + S5)

struct PrepArgs {
    const float* x0; const float* x1; const float* x2;
    const float* w[7];
};

__device__ __forceinline__ void split_store4(float4 v, __nv_bfloat16* h, __nv_bfloat16* l,
                                             size_t idx) {
    float a[4] = {v.x, v.y, v.z, v.w};
    __nv_bfloat16 hh[4], ll[4];
#pragma unroll
    for (int j = 0; j < 4; ++j) {
        hh[j] = __float2bfloat16(a[j]);
        ll[j] = __float2bfloat16(a[j] - __bfloat162float(hh[j]));
    }
    __nv_bfloat162 h0; h0.x = hh[0]; h0.y = hh[1];
    __nv_bfloat162 h1; h1.x = hh[2]; h1.y = hh[3];
    __nv_bfloat162 l0; l0.x = ll[0]; l0.y = ll[1];
    __nv_bfloat162 l1; l1.x = ll[2]; l1.y = ll[3];
    ((__nv_bfloat162*)(h + idx))[0] = h0;
    ((__nv_bfloat162*)(h + idx))[1] = h1;
    ((__nv_bfloat162*)(l + idx))[0] = l0;
    ((__nv_bfloat162*)(l + idx))[1] = l1;
}

__device__ __forceinline__ float4 pool4f(const float* in, int i, int Hc, int f) {
    int Wc = Hc;
    int c4 = i & 63;
    int r = i >> 6;
    int q = r % Wc; r /= Wc;
    int p = r % Hc;
    int b = r / Hc;
    int Win = Wc * f;
    const float4* in4 = (const float4*)in;
    float4 s = make_float4(0.f, 0.f, 0.f, 0.f);
    for (int dy = 0; dy < f; ++dy)
        for (int dx = 0; dx < f; ++dx) {
            float4 v = in4[(size_t)((b * Hc * f + p * f + dy) * Win + q * f + dx) * 64 + c4];
            s.x += v.x; s.y += v.y; s.z += v.z; s.w += v.w;
        }
    return s;
}

__global__ void prep_kernel(PrepArgs pa) {
    int i = blockIdx.x * blockDim.x + threadIdx.x;
    const int VOFF = 256 * 256;
    if (i < S0) {
        split_store4(pool4f(pa.x0, i, 4, 4), g_P0h, g_P0l, (size_t)i * 4);
    } else if ((i -= S0) < S1) {
        split_store4(pool4f(pa.x1, i, 16, 2), g_Pah, g_Pal, (size_t)i * 4);
    } else if ((i -= S1) < S2) {
        split_store4(pool4f(pa.x2, i, 32, 2), g_Pbh, g_Pbl, (size_t)i * 4);
    } else if ((i -= S2) < S3) {
        split_store4(((const float4*)pa.x0)[i], g_X0h, g_X0l, (size_t)i * 4);
    } else if ((i -= S3) < S4) {
        split_store4(((const float4*)pa.x1)[i], g_X1h, g_X1l, (size_t)i * 4);
    } else if ((i -= S4) < S5) {
        int e = i * 4;
        int mat = e >> 16;
        int off = e & 65535;
        float4 v = *(const float4*)&pa.w[mat][VOFF + off];
        split_store4(v, g_Wh + ((size_t)mat << 16), g_Wl + ((size_t)mat << 16), off);
    }
}

// ---------------------------------------------------------------------------
// Warp-MMA GEMM. out[m,n] = sum_k A[m,k]*W[n,k], split bf16 (hh+hl+lh).
// BM=128, BN=128, BK=32, 8 warps (64x32 each), 2-stage cp.async pipeline.
// smem tiles row stride 80B -> conflict-free ldmatrix.
// mode 0: plain store; 1: scatter-up by F; 2: gather-add Cadd[coarse(m)].
// ---------------------------------------------------------------------------
struct TCJob {
    const __nv_bfloat16 *A1h, *A1l, *A2h, *A2l;
    const __nv_bfloat16 *W1h, *W1l, *W2h, *W2l;
    float* out;
    const float* Cadd;
    int tile_end, Hc, Wc, F, mode;
};
struct TCJobs { TCJob j[3]; int njobs; };

#define RSTR 80                 // smem row stride (bytes) for 32 bf16 + pad
#define T_AH 0
#define T_AL (128 * RSTR)       // 10240
#define T_BH (2 * 128 * RSTR)   // 20480
#define T_BL (3 * 128 * RSTR)   // 30720
#define STG_BYTES (4 * 128 * RSTR)  // 40960
#define SMEM_TOTAL (2 * STG_BYTES)  // 81920

__global__ void __launch_bounds__(256, 2)
gemm_tc(TCJobs jobs) {
    extern __shared__ char smem[];
    const uint32_t sb = smem_to_u32(smem);
    const int tid = threadIdx.x;
    const int lid = tid & 31;
    const int wid = tid >> 5;
    const int wm = wid >> 2;       // 0..1
    const int wn = wid & 3;        // 0..3

    const int bt = blockIdx.x;
    int ji = 0;
    if (jobs.njobs > 1 && bt >= jobs.j[0].tile_end) ji = 1;
    if (jobs.njobs > 2 && bt >= jobs.j[1].tile_end) ji = 2;
    const TCJob jb = jobs.j[ji];
    const int local = bt - (ji == 0 ? 0 : jobs.j[ji - 1].tile_end);
    const int m0 = (local >> 1) * 128;
    const int n0 = (local & 1) * 128;

    const int nch = jb.A2h ? 16 : 8;

    float acc[4][4][4];
#pragma unroll
    for (int a = 0; a < 4; ++a)
#pragma unroll
        for (int b = 0; b < 4; ++b)
#pragma unroll
            for (int c = 0; c < 4; ++c) acc[a][b][c] = 0.f;

    // chunk loader: 8 cp16 per thread (2 rows x 4 tiles)
    const int lr = tid >> 2;       // 0..63
    const int lc = tid & 3;        // 16B chunk within 64B row
    auto load_chunk = [&](int c, int stage) {
        const __nv_bfloat16 *Ah, *Al, *Bh, *Bl;
        if (c < 8) { Ah = jb.A1h; Al = jb.A1l; Bh = jb.W1h; Bl = jb.W1l; }
        else       { Ah = jb.A2h; Al = jb.A2l; Bh = jb.W2h; Bl = jb.W2l; }
        const int k0 = (c & 7) * 32;
        const uint32_t s0 = sb + stage * STG_BYTES;
#pragma unroll
        for (int rr = 0; rr < 2; ++rr) {
            const int r = lr + rr * 64;
            const uint32_t so = r * RSTR + lc * 16;
            const size_t gA = (size_t)(m0 + r) * 256 + k0 + lc * 8;
            const size_t gB = (size_t)(n0 + r) * 256 + k0 + lc * 8;
            cp16(s0 + T_AH + so, Ah + gA);
            cp16(s0 + T_AL + so, Al + gA);
            cp16(s0 + T_BH + so, Bh + gB);
            cp16(s0 + T_BL + so, Bl + gB);
        }
    };

    load_chunk(0, 0);
    cp_commit();

    const uint32_t aoff = (wm * 64 + (lid & 15)) * RSTR + ((lid >> 4) & 1) * 16;
    const uint32_t boff = (wn * 32 + (lid & 7)) * RSTR + ((lid >> 3) & 1) * 16;

#pragma unroll 1
    for (int c = 0; c < nch; ++c) {
        if (c + 1 < nch) {
            load_chunk(c + 1, (c + 1) & 1);
            cp_commit();
            cp_wait<1>();
        } else {
            cp_wait<0>();
        }
        __syncthreads();
        const uint32_t s0 = sb + (c & 1) * STG_BYTES;
#pragma unroll
        for (int ks = 0; ks < 2; ++ks) {
            const uint32_t kb = ks * 32;   // 16 bf16 = 32B per k-step
            uint32_t bh[4][2], bl[4][2];
#pragma unroll
            for (int ni = 0; ni < 4; ++ni) {
                ldsm2(bh[ni], s0 + T_BH + boff + ni * 8 * RSTR + kb);
                ldsm2(bl[ni], s0 + T_BL + boff + ni * 8 * RSTR + kb);
            }
#pragma unroll
            for (int mi = 0; mi < 4; ++mi) {
                uint32_t ah[4], al[4];
                ldsm4(ah, s0 + T_AH + aoff + mi * 16 * RSTR + kb);
                ldsm4(al, s0 + T_AL + aoff + mi * 16 * RSTR + kb);
#pragma unroll
                for (int ni = 0; ni < 4; ++ni) {
                    mma16816(acc[mi][ni], ah, bh[ni]);
                    mma16816(acc[mi][ni], ah, bl[ni]);
                    mma16816(acc[mi][ni], al, bh[ni]);
                }
            }
        }
        __syncthreads();
    }

    // Epilogue. D frag: lane holds (row g, col 2tg), (row g+8) pairs.
    const int g = lid >> 2;
    const int tg = lid & 3;
#pragma unroll
    for (int mi = 0; mi < 4; ++mi) {
#pragma unroll
        for (int half = 0; half < 2; ++half) {
            const int rm = m0 + wm * 64 + mi * 16 + g + half * 8;
            if (jb.mode == 0) {
                float* dst = jb.out + (size_t)rm * 256;
#pragma unroll
                for (int ni = 0; ni < 4; ++ni) {
                    const int cn = n0 + wn * 32 + ni * 8 + tg * 2;
                    *(float2*)(dst + cn) = make_float2(acc[mi][ni][half * 2],
                                                       acc[mi][ni][half * 2 + 1]);
                }
            } else if (jb.mode == 1) {
                const int HW = jb.Hc * jb.Wc;
                const int b = rm / HW;
                const int rem = rm - b * HW;
                const int h = rem / jb.Wc;
                const int w = rem - h * jb.Wc;
                const int Wf = jb.Wc * jb.F;
                for (int dy = 0; dy < jb.F; ++dy)
                    for (int dx = 0; dx < jb.F; ++dx) {
                        size_t fm = (size_t)(b * jb.Hc * jb.F + h * jb.F + dy) * Wf
                                    + (w * jb.F + dx);
                        float* dst = jb.out + fm * 256;
#pragma unroll
                        for (int ni = 0; ni < 4; ++ni) {
                            const int cn = n0 + wn * 32 + ni * 8 + tg * 2;
                            *(float2*)(dst + cn) = make_float2(acc[mi][ni][half * 2],
                                                               acc[mi][ni][half * 2 + 1]);
                        }
                    }
            } else {
                const int Wf = jb.Wc * jb.F;
                const int HWf = jb.Hc * jb.F * Wf;
                const int b = rm / HWf;
                const int rem = rm - b * HWf;
                const int h = rem / Wf;
                const int w = rem - h * Wf;
                const int crow = (b * jb.Hc + h / jb.F) * jb.Wc + (w / jb.F);
                const float* csrc = jb.Cadd + (size_t)crow * 256;
                float* dst = jb.out + (size_t)rm * 256;
#pragma unroll
                for (int ni = 0; ni < 4; ++ni) {
                    const int cn = n0 + wn * 32 + ni * 8 + tg * 2;
                    float2 cv = *(const float2*)(csrc + cn);
                    *(float2*)(dst + cn) = make_float2(acc[mi][ni][half * 2] + cv.x,
                                                       acc[mi][ni][half * 2 + 1] + cv.y);
                }
            }
        }
    }
}

// ---------------------------------------------------------------------------
// Launch
// ---------------------------------------------------------------------------
extern "C" void kernel_launch(void* const* d_in, const int* in_sizes, int n_in,
                              void* d_out, int out_size) {
    (void)n_in; (void)out_size;

    const float* x0 = (const float*)d_in[0];   // [8,16,16,256]
    const float* x1 = (const float*)d_in[1];   // [8,32,32,256]
    const float* x2 = (const float*)d_in[2];   // [8,64,64,256]

    // setup_inputs() builds the dict INTERLEAVED (qpeer_w0, kvpeer_w0, ...).
    // Disambiguate by element count: kv = 512*256, q = 256*256.
    const bool inter = (in_sizes[4] == 2 * 256 * 256);
    const float* kvpeer0 = (const float*)d_in[inter ? 4  : 6];
    const float* kvpeer1 = (const float*)d_in[inter ? 6  : 7];
    const float* kvpeer2 = (const float*)d_in[inter ? 8  : 8];
    const float* kvpar1  = (const float*)d_in[inter ? 10 : 11];
    const float* kvpar2  = (const float*)d_in[inter ? 12 : 12];
    const float* kvkid0  = (const float*)d_in[inter ? 14 : 15];
    const float* kvkid1  = (const float*)d_in[inter ? 16 : 16];

    __nv_bfloat16 *P0h, *P0l, *Pah, *Pal, *Pbh, *Pbl, *X0h, *X0l, *X1h, *X1l, *Wh, *Wl;
    float *C0, *C1;
    cudaGetSymbolAddress((void**)&P0h, g_P0h); cudaGetSymbolAddress((void**)&P0l, g_P0l);
    cudaGetSymbolAddress((void**)&Pah, g_Pah); cudaGetSymbolAddress((void**)&Pal, g_Pal);
    cudaGetSymbolAddress((void**)&Pbh, g_Pbh); cudaGetSymbolAddress((void**)&Pbl, g_Pbl);
    cudaGetSymbolAddress((void**)&X0h, g_X0h); cudaGetSymbolAddress((void**)&X0l, g_X0l);
    cudaGetSymbolAddress((void**)&X1h, g_X1h); cudaGetSymbolAddress((void**)&X1l, g_X1l);
    cudaGetSymbolAddress((void**)&Wh, g_Wh);   cudaGetSymbolAddress((void**)&Wl, g_Wl);
    cudaGetSymbolAddress((void**)&C0, g_C0);   cudaGetSymbolAddress((void**)&C1, g_C1);

    float* out0 = (float*)d_out;                 // 8*16*16*256
    float* out1 = out0 + 8 * 16 * 16 * 256;      // 8*32*32*256
    float* out2 = out1 + 8 * 32 * 32 * 256;      // 8*64*64*256

    cudaFuncSetAttribute(gemm_tc, cudaFuncAttributeMaxDynamicSharedMemorySize, SMEM_TOTAL);

    // 1) prep: pools + bf16 hi/lo splits
    PrepArgs pa;
    pa.x0 = x0; pa.x1 = x1; pa.x2 = x2;
    pa.w[0] = kvpeer0; pa.w[1] = kvpeer1; pa.w[2] = kvpeer2;
    pa.w[3] = kvpar1;  pa.w[4] = kvpar2;  pa.w[5] = kvkid0;  pa.w[6] = kvkid1;
    prep_kernel<<<PREP_TOTAL / 256, 256>>>(pa);

    __nv_bfloat16* W0h = Wh;            __nv_bfloat16* W0l = Wl;             // peer0
    __nv_bfloat16* W1h = Wh + 65536;    __nv_bfloat16* W1l = Wl + 65536;     // peer1
    __nv_bfloat16* W2h = Wh + 131072;   __nv_bfloat16* W2l = Wl + 131072;    // peer2
    __nv_bfloat16* W3h = Wh + 196608;   __nv_bfloat16* W3l = Wl + 196608;    // par1
    __nv_bfloat16* W4h = Wh + 262144;   __nv_bfloat16* W4l = Wl + 262144;    // par2
    __nv_bfloat16* W5h = Wh + 327680;   __nv_bfloat16* W5l = Wl + 327680;    // kid0
    __nv_bfloat16* W6h = Wh + 393216;   __nv_bfloat16* W6l = Wl + 393216;    // kid1

    // 2) coarse: C0 = P0@Wp0^T ; C1 = Pa@Wp1^T + x0@Wpar1^T ;
    //    out2 = up2(Pb@Wp2^T + x1@Wpar2^T)
    TCJobs cj;
    cj.njobs = 3;
    cj.j[0] = { P0h, P0l, nullptr, nullptr, W0h, W0l, nullptr, nullptr, C0,   nullptr, 2,   0,  0,  0, 0 };
    cj.j[1] = { Pah, Pal, X0h, X0l,          W1h, W1l, W3h, W3l,         C1,   nullptr, 34,  0,  0,  0, 0 };
    cj.j[2] = { Pbh, Pbl, X1h, X1l,          W2h, W2l, W4h, W4l,         out2, nullptr, 162, 32, 32, 2, 1 };
    gemm_tc<<<162, 256, SMEM_TOTAL>>>(cj);

    // 3) fine: out0 = Pa@Wk0^T + up4(C0) ; out1 = Pb@Wk1^T + up2(C1)
    TCJobs fj;
    fj.njobs = 2;
    fj.j[0] = { Pah, Pal, nullptr, nullptr, W5h, W5l, nullptr, nullptr, out0, C0, 32,  4,  4,  4, 2 };
    fj.j[1] = { Pbh, Pbl, nullptr, nullptr, W6h, W6l, nullptr, nullptr, out1, C1, 160, 16, 16, 2, 2 };
    fj.j[2] = fj.j[1];
    gemm_tc<<<160, 256, SMEM_TOTAL>>>(fj);
}

// round 7
// speedup vs baseline: 4.1061x; 1.5393x over previous
#include <cuda_runtime.h>
#include <cuda_fp16.h>
#include <cstdint>

// ---------------------------------------------------------------------------
// MSAttention: einsum 'bkhwlm,bkhwlnf->bkhwlf' factorizes as
// (sum_m A)*(sum_n V) = 1 * sum_n V  =>  attention is dead code. Output is a
// sum of V-projections of (block-sum) pooled inputs:
//   out0 = Wvkid0*pool2(x1) + up4( Wvpeer0*pool4(x0) )
//   out1 = Wvkid1*pool2(x2) + up2( Wvpeer1*pool2(x1) + Wvpar1*x0 )
//   out2 =                    up2( Wvpeer2*pool2(x2) + Wvpar2*x1 )
// Wv* = rows [256,512) of the kv weights.
//
// GEMMs via mma.sync m16n8k16 fp16 (fp32 accum). fp16 quantization gives
// ~3e-4 rel error (vs 1e-3 gate); 1 MMA per k-step instead of the 3 needed
// for split-bf16 => 3x less tensor work on the de-rated legacy HMMA path.
// ---------------------------------------------------------------------------

// ---- scratch (fp16 operand copies) ----
__device__ __half g_P0[128 * 256];
__device__ __half g_Pa[2048 * 256];
__device__ __half g_Pb[8192 * 256];
__device__ __half g_X0[2048 * 256];
__device__ __half g_X1[8192 * 256];
__device__ __half g_W[7 * 65536];
__device__ float g_C0[128 * 256];
__device__ float g_C1[2048 * 256];

// ---------------------------------------------------------------------------
// PTX helpers (baseline features only: harness ptxas targets sm_103, no 'a')
// ---------------------------------------------------------------------------
__device__ __forceinline__ uint32_t smem_to_u32(const void* p) {
    uint32_t a;
    asm("{ .reg .u64 t; cvta.to.shared.u64 t, %1; cvt.u32.u64 %0, t; }" : "=r"(a) : "l"(p));
    return a;
}
__device__ __forceinline__ void cp16(uint32_t smem, const void* gmem) {
    asm volatile("cp.async.cg.shared.global [%0], [%1], 16;" :: "r"(smem), "l"(gmem));
}
__device__ __forceinline__ void cp_commit() {
    asm volatile("cp.async.commit_group;" ::: "memory");
}
template <int N>
__device__ __forceinline__ void cp_wait() {
    asm volatile("cp.async.wait_group %0;" :: "n"(N) : "memory");
}
__device__ __forceinline__ void ldsm4(uint32_t* r, uint32_t addr) {
    asm volatile("ldmatrix.sync.aligned.m8n8.x4.shared.b16 {%0,%1,%2,%3}, [%4];"
                 : "=r"(r[0]), "=r"(r[1]), "=r"(r[2]), "=r"(r[3]) : "r"(addr));
}
__device__ __forceinline__ void ldsm2(uint32_t* r, uint32_t addr) {
    asm volatile("ldmatrix.sync.aligned.m8n8.x2.shared.b16 {%0,%1}, [%2];"
                 : "=r"(r[0]), "=r"(r[1]) : "r"(addr));
}
__device__ __forceinline__ void mma16816(float* d, const uint32_t* a, const uint32_t* b) {
    asm volatile(
        "mma.sync.aligned.m16n8k16.row.col.f32.f16.f16.f32 "
        "{%0,%1,%2,%3}, {%4,%5,%6,%7}, {%8,%9}, {%0,%1,%2,%3};"
        : "+f"(d[0]), "+f"(d[1]), "+f"(d[2]), "+f"(d[3])
        : "r"(a[0]), "r"(a[1]), "r"(a[2]), "r"(a[3]), "r"(b[0]), "r"(b[1]));
}

// ---------------------------------------------------------------------------
// Prep kernel: pools + fp32->fp16 conversions (A operands and V-weights).
// ---------------------------------------------------------------------------
#define S0 8192        // P0 pool  (f=4 from x0)
#define S1 131072      // Pa pool  (f=2 from x1)
#define S2 524288      // Pb pool  (f=2 from x2)
#define S3 131072      // X0 copy
#define S4 524288      // X1 copy
#define S5 114688      // weights 7 * 65536 / 4
#define PREP_TOTAL (S0 + S1 + S2 + S3 + S4 + S5)

struct PrepArgs {
    const float* x0; const float* x1; const float* x2;
    const float* w[7];
};

__device__ __forceinline__ void conv_store4(float4 v, __half* h, size_t idx) {
    __half2* p = (__half2*)(h + idx);
    p[0] = __floats2half2_rn(v.x, v.y);
    p[1] = __floats2half2_rn(v.z, v.w);
}

__device__ __forceinline__ float4 pool4f(const float* in, int i, int Hc, int f) {
    int Wc = Hc;
    int c4 = i & 63;
    int r = i >> 6;
    int q = r % Wc; r /= Wc;
    int p = r % Hc;
    int b = r / Hc;
    int Win = Wc * f;
    const float4* in4 = (const float4*)in;
    float4 s = make_float4(0.f, 0.f, 0.f, 0.f);
    for (int dy = 0; dy < f; ++dy)
        for (int dx = 0; dx < f; ++dx) {
            float4 v = in4[(size_t)((b * Hc * f + p * f + dy) * Win + q * f + dx) * 64 + c4];
            s.x += v.x; s.y += v.y; s.z += v.z; s.w += v.w;
        }
    return s;
}

__global__ void prep_kernel(PrepArgs pa) {
    int i = blockIdx.x * blockDim.x + threadIdx.x;
    const int VOFF = 256 * 256;
    if (i < S0) {
        conv_store4(pool4f(pa.x0, i, 4, 4), g_P0, (size_t)i * 4);
    } else if ((i -= S0) < S1) {
        conv_store4(pool4f(pa.x1, i, 16, 2), g_Pa, (size_t)i * 4);
    } else if ((i -= S1) < S2) {
        conv_store4(pool4f(pa.x2, i, 32, 2), g_Pb, (size_t)i * 4);
    } else if ((i -= S2) < S3) {
        conv_store4(((const float4*)pa.x0)[i], g_X0, (size_t)i * 4);
    } else if ((i -= S3) < S4) {
        conv_store4(((const float4*)pa.x1)[i], g_X1, (size_t)i * 4);
    } else if ((i -= S4) < S5) {
        int e = i * 4;
        int mat = e >> 16;
        int off = e & 65535;
        float4 v = *(const float4*)&pa.w[mat][VOFF + off];
        conv_store4(v, g_W + ((size_t)mat << 16), off);
    }
}

// ---------------------------------------------------------------------------
// Warp-MMA GEMM. out[m,n] = sum_k A[m,k]*W[n,k], fp16 in / fp32 acc.
// BM=128, BN=128, BK=32, 8 warps (64x32 each), 2-stage cp.async pipeline.
// smem row stride 80B -> conflict-free ldmatrix.
// mode 0: plain store; 1: scatter-up by F; 2: gather-add Cadd[coarse(m)].
// ---------------------------------------------------------------------------
struct TCJob {
    const __half *A1, *A2, *W1, *W2;
    float* out;
    const float* Cadd;
    int tile_end, Hc, Wc, F, mode;
};
struct TCJobs { TCJob j[3]; int njobs; };

#define RSTR 80                  // smem row stride (bytes): 64B data + 16 pad
#define T_A 0
#define T_B (128 * RSTR)         // 10240
#define STG_BYTES (2 * 128 * RSTR)   // 20480
#define SMEM_TOTAL (2 * STG_BYTES)   // 40960

__global__ void __launch_bounds__(256, 2)
gemm_tc(TCJobs jobs) {
    extern __shared__ char smem[];
    const uint32_t sb = smem_to_u32(smem);
    const int tid = threadIdx.x;
    const int lid = tid & 31;
    const int wid = tid >> 5;
    const int wm = wid >> 2;       // 0..1
    const int wn = wid & 3;        // 0..3

    const int bt = blockIdx.x;
    int ji = 0;
    if (jobs.njobs > 1 && bt >= jobs.j[0].tile_end) ji = 1;
    if (jobs.njobs > 2 && bt >= jobs.j[1].tile_end) ji = 2;
    const TCJob jb = jobs.j[ji];
    const int local = bt - (ji == 0 ? 0 : jobs.j[ji - 1].tile_end);
    const int m0 = (local >> 1) * 128;
    const int n0 = (local & 1) * 128;

    const int nch = jb.A2 ? 16 : 8;

    float acc[4][4][4];
#pragma unroll
    for (int a = 0; a < 4; ++a)
#pragma unroll
        for (int b = 0; b < 4; ++b)
#pragma unroll
            for (int c = 0; c < 4; ++c) acc[a][b][c] = 0.f;

    // chunk loader: 4 cp16 per thread (2 rows x 2 tiles)
    const int lr = tid >> 2;       // 0..63
    const int lc = tid & 3;        // 16B chunk within 64B row
    auto load_chunk = [&](int c, int stage) {
        const __half* A = (c < 8) ? jb.A1 : jb.A2;
        const __half* B = (c < 8) ? jb.W1 : jb.W2;
        const int k0 = (c & 7) * 32;
        const uint32_t s0 = sb + stage * STG_BYTES;
#pragma unroll
        for (int rr = 0; rr < 2; ++rr) {
            const int r = lr + rr * 64;
            const uint32_t so = r * RSTR + lc * 16;
            cp16(s0 + T_A + so, A + (size_t)(m0 + r) * 256 + k0 + lc * 8);
            cp16(s0 + T_B + so, B + (size_t)(n0 + r) * 256 + k0 + lc * 8);
        }
    };

    load_chunk(0, 0);
    cp_commit();

    const uint32_t aoff = (wm * 64 + (lid & 15)) * RSTR + ((lid >> 4) & 1) * 16;
    const uint32_t boff = (wn * 32 + (lid & 7)) * RSTR + ((lid >> 3) & 1) * 16;

#pragma unroll 1
    for (int c = 0; c < nch; ++c) {
        if (c + 1 < nch) {
            load_chunk(c + 1, (c + 1) & 1);
            cp_commit();
            cp_wait<1>();
        } else {
            cp_wait<0>();
        }
        __syncthreads();
        const uint32_t s0 = sb + (c & 1) * STG_BYTES;
#pragma unroll
        for (int ks = 0; ks < 2; ++ks) {
            const uint32_t kb = ks * 32;   // 16 fp16 = 32B per k-step
            uint32_t b[4][2];
#pragma unroll
            for (int ni = 0; ni < 4; ++ni)
                ldsm2(b[ni], s0 + T_B + boff + ni * 8 * RSTR + kb);
#pragma unroll
            for (int mi = 0; mi < 4; ++mi) {
                uint32_t a[4];
                ldsm4(a, s0 + T_A + aoff + mi * 16 * RSTR + kb);
#pragma unroll
                for (int ni = 0; ni < 4; ++ni)
                    mma16816(acc[mi][ni], a, b[ni]);
            }
        }
        __syncthreads();
    }

    // Epilogue. D frag: lane holds (row g, col 2tg), (row g+8) pairs.
    const int g = lid >> 2;
    const int tg = lid & 3;
#pragma unroll
    for (int mi = 0; mi < 4; ++mi) {
#pragma unroll
        for (int half = 0; half < 2; ++half) {
            const int rm = m0 + wm * 64 + mi * 16 + g + half * 8;
            if (jb.mode == 0) {
                float* dst = jb.out + (size_t)rm * 256;
#pragma unroll
                for (int ni = 0; ni < 4; ++ni) {
                    const int cn = n0 + wn * 32 + ni * 8 + tg * 2;
                    *(float2*)(dst + cn) = make_float2(acc[mi][ni][half * 2],
                                                       acc[mi][ni][half * 2 + 1]);
                }
            } else if (jb.mode == 1) {
                const int HW = jb.Hc * jb.Wc;
                const int b = rm / HW;
                const int rem = rm - b * HW;
                const int h = rem / jb.Wc;
                const int w = rem - h * jb.Wc;
                const int Wf = jb.Wc * jb.F;
                for (int dy = 0; dy < jb.F; ++dy)
                    for (int dx = 0; dx < jb.F; ++dx) {
                        size_t fm = (size_t)(b * jb.Hc * jb.F + h * jb.F + dy) * Wf
                                    + (w * jb.F + dx);
                        float* dst = jb.out + fm * 256;
#pragma unroll
                        for (int ni = 0; ni < 4; ++ni) {
                            const int cn = n0 + wn * 32 + ni * 8 + tg * 2;
                            *(float2*)(dst + cn) = make_float2(acc[mi][ni][half * 2],
                                                               acc[mi][ni][half * 2 + 1]);
                        }
                    }
            } else {
                const int Wf = jb.Wc * jb.F;
                const int HWf = jb.Hc * jb.F * Wf;
                const int b = rm / HWf;
                const int rem = rm - b * HWf;
                const int h = rem / Wf;
                const int w = rem - h * Wf;
                const int crow = (b * jb.Hc + h / jb.F) * jb.Wc + (w / jb.F);
                const float* csrc = jb.Cadd + (size_t)crow * 256;
                float* dst = jb.out + (size_t)rm * 256;
#pragma unroll
                for (int ni = 0; ni < 4; ++ni) {
                    const int cn = n0 + wn * 32 + ni * 8 + tg * 2;
                    float2 cv = *(const float2*)(csrc + cn);
                    *(float2*)(dst + cn) = make_float2(acc[mi][ni][half * 2] + cv.x,
                                                       acc[mi][ni][half * 2 + 1] + cv.y);
                }
            }
        }
    }
}

// ---------------------------------------------------------------------------
// Launch
// ---------------------------------------------------------------------------
extern "C" void kernel_launch(void* const* d_in, const int* in_sizes, int n_in,
                              void* d_out, int out_size) {
    (void)n_in; (void)out_size;

    const float* x0 = (const float*)d_in[0];   // [8,16,16,256]
    const float* x1 = (const float*)d_in[1];   // [8,32,32,256]
    const float* x2 = (const float*)d_in[2];   // [8,64,64,256]

    // setup_inputs() builds the dict INTERLEAVED (qpeer_w0, kvpeer_w0, ...).
    // Disambiguate by element count: kv = 512*256, q = 256*256.
    const bool inter = (in_sizes[4] == 2 * 256 * 256);
    const float* kvpeer0 = (const float*)d_in[inter ? 4  : 6];
    const float* kvpeer1 = (const float*)d_in[inter ? 6  : 7];
    const float* kvpeer2 = (const float*)d_in[inter ? 8  : 8];
    const float* kvpar1  = (const float*)d_in[inter ? 10 : 11];
    const float* kvpar2  = (const float*)d_in[inter ? 12 : 12];
    const float* kvkid0  = (const float*)d_in[inter ? 14 : 15];
    const float* kvkid1  = (const float*)d_in[inter ? 16 : 16];

    __half *P0, *Pa, *Pb, *X0, *X1, *W;
    float *C0, *C1;
    cudaGetSymbolAddress((void**)&P0, g_P0);
    cudaGetSymbolAddress((void**)&Pa, g_Pa);
    cudaGetSymbolAddress((void**)&Pb, g_Pb);
    cudaGetSymbolAddress((void**)&X0, g_X0);
    cudaGetSymbolAddress((void**)&X1, g_X1);
    cudaGetSymbolAddress((void**)&W, g_W);
    cudaGetSymbolAddress((void**)&C0, g_C0);
    cudaGetSymbolAddress((void**)&C1, g_C1);

    float* out0 = (float*)d_out;                 // 8*16*16*256
    float* out1 = out0 + 8 * 16 * 16 * 256;      // 8*32*32*256
    float* out2 = out1 + 8 * 32 * 32 * 256;      // 8*64*64*256

    cudaFuncSetAttribute(gemm_tc, cudaFuncAttributeMaxDynamicSharedMemorySize, SMEM_TOTAL);

    // 1) prep: pools + fp16 conversions
    PrepArgs pa;
    pa.x0 = x0; pa.x1 = x1; pa.x2 = x2;
    pa.w[0] = kvpeer0; pa.w[1] = kvpeer1; pa.w[2] = kvpeer2;
    pa.w[3] = kvpar1;  pa.w[4] = kvpar2;  pa.w[5] = kvkid0;  pa.w[6] = kvkid1;
    prep_kernel<<<PREP_TOTAL / 256, 256>>>(pa);

    __half* W0 = W;             // peer0
    __half* W1 = W + 65536;     // peer1
    __half* W2 = W + 131072;    // peer2
    __half* W3 = W + 196608;    // par1
    __half* W4 = W + 262144;    // par2
    __half* W5 = W + 327680;    // kid0
    __half* W6 = W + 393216;    // kid1

    // 2) coarse: C0 = P0@Wp0^T ; C1 = Pa@Wp1^T + x0@Wpar1^T ;
    //    out2 = up2(Pb@Wp2^T + x1@Wpar2^T)
    TCJobs cj;
    cj.njobs = 3;
    cj.j[0] = { P0, nullptr, W0, nullptr, C0,   nullptr, 2,   0,  0,  0, 0 };
    cj.j[1] = { Pa, X0,      W1, W3,      C1,   nullptr, 34,  0,  0,  0, 0 };
    cj.j[2] = { Pb, X1,      W2, W4,      out2, nullptr, 162, 32, 32, 2, 1 };
    gemm_tc<<<162, 256, SMEM_TOTAL>>>(cj);

    // 3) fine: out0 = Pa@Wk0^T + up4(C0) ; out1 = Pb@Wk1^T + up2(C1)
    TCJobs fj;
    fj.njobs = 2;
    fj.j[0] = { Pa, nullptr, W5, nullptr, out0, C0, 32,  4,  4,  4, 2 };
    fj.j[1] = { Pb, nullptr, W6, nullptr, out1, C1, 160, 16, 16, 2, 2 };
    fj.j[2] = fj.j[1];
    gemm_tc<<<160, 256, SMEM_TOTAL>>>(fj);
}

// round 8
// speedup vs baseline: 4.3846x; 1.0678x over previous
#include <cuda_runtime.h>
#include <cuda_fp16.h>
#include <cstdint>

// ---------------------------------------------------------------------------
// MSAttention: einsum 'bkhwlm,bkhwlnf->bkhwlf' factorizes as
// (sum_m A)*(sum_n V) = 1 * sum_n V  =>  attention is dead code. Output is a
// sum of V-projections of (block-sum) pooled inputs:
//   out0 = Wvkid0*pool2(x1) + up4( Wvpeer0*pool4(x0) )
//   out1 = Wvkid1*pool2(x2) + up2( Wvpeer1*pool2(x1) + Wvpar1*x0 )
//   out2 =                    up2( Wvpeer2*pool2(x2) + Wvpar2*x1 )
// Wv* = rows [256,512) of the kv weights.
//
// GEMMs via mma.sync m16n8k16 fp16 (fp32 accum), 3-stage cp.async pipeline,
// one __syncthreads per k-chunk. The parent operands (x0/x1) are loaded fp32
// directly from the inputs and converted in-register (no fp16 staging copy).
// ---------------------------------------------------------------------------

// ---- scratch (fp16 operand copies) ----
__device__ __half g_P0[128 * 256];
__device__ __half g_Pa[2048 * 256];
__device__ __half g_Pb[8192 * 256];
__device__ __half g_W[7 * 65536];
__device__ float g_C0[128 * 256];
__device__ float g_C1[2048 * 256];

// ---------------------------------------------------------------------------
// PTX helpers (baseline features only: harness ptxas targets sm_103, no 'a')
// ---------------------------------------------------------------------------
__device__ __forceinline__ uint32_t smem_to_u32(const void* p) {
    uint32_t a;
    asm("{ .reg .u64 t; cvta.to.shared.u64 t, %1; cvt.u32.u64 %0, t; }" : "=r"(a) : "l"(p));
    return a;
}
__device__ __forceinline__ void cp16(uint32_t smem, const void* gmem) {
    asm volatile("cp.async.cg.shared.global [%0], [%1], 16;" :: "r"(smem), "l"(gmem));
}
__device__ __forceinline__ void cp_commit() {
    asm volatile("cp.async.commit_group;" ::: "memory");
}
template <int N>
__device__ __forceinline__ void cp_wait() {
    asm volatile("cp.async.wait_group %0;" :: "n"(N) : "memory");
}
__device__ __forceinline__ void ldsm4(uint32_t* r, uint32_t addr) {
    asm volatile("ldmatrix.sync.aligned.m8n8.x4.shared.b16 {%0,%1,%2,%3}, [%4];"
                 : "=r"(r[0]), "=r"(r[1]), "=r"(r[2]), "=r"(r[3]) : "r"(addr));
}
__device__ __forceinline__ void ldsm2(uint32_t* r, uint32_t addr) {
    asm volatile("ldmatrix.sync.aligned.m8n8.x2.shared.b16 {%0,%1}, [%2];"
                 : "=r"(r[0]), "=r"(r[1]) : "r"(addr));
}
__device__ __forceinline__ void mma16816(float* d, const uint32_t* a, const uint32_t* b) {
    asm volatile(
        "mma.sync.aligned.m16n8k16.row.col.f32.f16.f16.f32 "
        "{%0,%1,%2,%3}, {%4,%5,%6,%7}, {%8,%9}, {%0,%1,%2,%3};"
        : "+f"(d[0]), "+f"(d[1]), "+f"(d[2]), "+f"(d[3])
        : "r"(a[0]), "r"(a[1]), "r"(a[2]), "r"(a[3]), "r"(b[0]), "r"(b[1]));
}

// ---------------------------------------------------------------------------
// Prep kernel: pools + fp32->fp16 conversions (pooled operands and V-weights).
// ---------------------------------------------------------------------------
#define S0 8192        // P0 pool  (f=4 from x0)
#define S1 131072      // Pa pool  (f=2 from x1)
#define S2 524288      // Pb pool  (f=2 from x2)
#define S5 114688      // weights 7 * 65536 / 4
#define PREP_TOTAL (S0 + S1 + S2 + S5)

struct PrepArgs {
    const float* x0; const float* x1; const float* x2;
    const float* w[7];
};

__device__ __forceinline__ void conv_store4(float4 v, __half* h, size_t idx) {
    __half2* p = (__half2*)(h + idx);
    p[0] = __floats2half2_rn(v.x, v.y);
    p[1] = __floats2half2_rn(v.z, v.w);
}

__device__ __forceinline__ float4 pool4f(const float* in, int i, int Hc, int f) {
    int Wc = Hc;
    int c4 = i & 63;
    int r = i >> 6;
    int q = r % Wc; r /= Wc;
    int p = r % Hc;
    int b = r / Hc;
    int Win = Wc * f;
    const float4* in4 = (const float4*)in;
    float4 s = make_float4(0.f, 0.f, 0.f, 0.f);
    for (int dy = 0; dy < f; ++dy)
        for (int dx = 0; dx < f; ++dx) {
            float4 v = in4[(size_t)((b * Hc * f + p * f + dy) * Win + q * f + dx) * 64 + c4];
            s.x += v.x; s.y += v.y; s.z += v.z; s.w += v.w;
        }
    return s;
}

__global__ void prep_kernel(PrepArgs pa) {
    int i = blockIdx.x * blockDim.x + threadIdx.x;
    const int VOFF = 256 * 256;
    if (i < S0) {
        conv_store4(pool4f(pa.x0, i, 4, 4), g_P0, (size_t)i * 4);
    } else if ((i -= S0) < S1) {
        conv_store4(pool4f(pa.x1, i, 16, 2), g_Pa, (size_t)i * 4);
    } else if ((i -= S1) < S2) {
        conv_store4(pool4f(pa.x2, i, 32, 2), g_Pb, (size_t)i * 4);
    } else if ((i -= S2) < S5) {
        int e = i * 4;
        int mat = e >> 16;
        int off = e & 65535;
        float4 v = *(const float4*)&pa.w[mat][VOFF + off];
        conv_store4(v, g_W + ((size_t)mat << 16), off);
    }
}

// ---------------------------------------------------------------------------
// Warp-MMA GEMM. out[m,n] = sum_k A[m,k]*W[n,k], fp16 in / fp32 acc.
// BM=128, BN=128, BK=32, 8 warps (64x32 each), 3-stage cp.async pipeline,
// ONE __syncthreads per chunk. K=512 jobs: chunks 8..15 take the A operand
// from fp32 global memory (A2f), converted in-register and STS'd after the
// current chunk's compute (visible 2 chunks later via the barrier chain).
// smem row stride 80B -> conflict-free ldmatrix.
// mode 0: plain store; 1: scatter-up by F; 2: gather-add Cadd[coarse(m)].
// ---------------------------------------------------------------------------
struct TCJob {
    const __half *A1, *W1, *W2;
    const float* A2f;
    float* out;
    const float* Cadd;
    int tile_end, Hc, Wc, F, mode;
};
struct TCJobs { TCJob j[3]; int njobs; };

#define RSTR 80                  // smem row stride (bytes): 64B data + 16 pad
#define T_A 0
#define T_B (128 * RSTR)             // 10240
#define STG_BYTES (2 * 128 * RSTR)   // 20480
#define SMEM_TOTAL (3 * STG_BYTES)   // 61440

__global__ void __launch_bounds__(256, 2)
gemm_tc(TCJobs jobs) {
    extern __shared__ char smem[];
    const uint32_t sb = smem_to_u32(smem);
    const int tid = threadIdx.x;
    const int lid = tid & 31;
    const int wid = tid >> 5;
    const int wm = wid >> 2;       // 0..1
    const int wn = wid & 3;        // 0..3

    const int bt = blockIdx.x;
    int ji = 0;
    if (jobs.njobs > 1 && bt >= jobs.j[0].tile_end) ji = 1;
    if (jobs.njobs > 2 && bt >= jobs.j[1].tile_end) ji = 2;
    const TCJob jb = jobs.j[ji];
    const int local = bt - (ji == 0 ? 0 : jobs.j[ji - 1].tile_end);
    const int m0 = (local >> 1) * 128;
    const int n0 = (local & 1) * 128;

    const int nch = jb.W2 ? 16 : 8;

    float acc[4][4][4];
#pragma unroll
    for (int a = 0; a < 4; ++a)
#pragma unroll
        for (int b = 0; b < 4; ++b)
#pragma unroll
            for (int c = 0; c < 4; ++c) acc[a][b][c] = 0.f;

    const int lr = tid >> 2;       // 0..63
    const int lc = tid & 3;        // 16B chunk within 64B row

    // async loads: B tile always; A tile only for chunks 0..7 (fp16 source)
    auto load_async = [&](int c, int stage) {
        const __half* B = (c < 8) ? jb.W1 : jb.W2;
        const int k0 = (c & 7) * 32;
        const uint32_t s0 = sb + stage * STG_BYTES;
#pragma unroll
        for (int rr = 0; rr < 2; ++rr) {
            const int r = lr + rr * 64;
            const uint32_t so = r * RSTR + lc * 16;
            cp16(s0 + T_B + so, B + (size_t)(n0 + r) * 256 + k0 + lc * 8);
            if (c < 8)
                cp16(s0 + T_A + so, jb.A1 + (size_t)(m0 + r) * 256 + k0 + lc * 8);
        }
    };
    // fp32 A loads for chunks 8..15 (staged in regs, STS'd after compute)
    auto ldg_a2 = [&](int c, float4* st) {
        const int k0 = (c & 7) * 32;
#pragma unroll
        for (int rr = 0; rr < 2; ++rr) {
            const float* g = jb.A2f + (size_t)(m0 + lr + rr * 64) * 256 + k0 + lc * 8;
            st[rr * 2 + 0] = ((const float4*)g)[0];
            st[rr * 2 + 1] = ((const float4*)g)[1];
        }
    };
    auto sts_a2 = [&](int stage, const float4* st) {
        char* s0 = smem + stage * STG_BYTES + T_A;
#pragma unroll
        for (int rr = 0; rr < 2; ++rr) {
            const uint32_t so = (lr + rr * 64) * RSTR + lc * 16;
            __half2* d = (__half2*)(s0 + so);
            float4 v0 = st[rr * 2 + 0];
            float4 v1 = st[rr * 2 + 1];
            d[0] = __floats2half2_rn(v0.x, v0.y);
            d[1] = __floats2half2_rn(v0.z, v0.w);
            d[2] = __floats2half2_rn(v1.x, v1.y);
            d[3] = __floats2half2_rn(v1.z, v1.w);
        }
    };

    // prologue: chunks 0,1 (always fp16 A path)
    load_async(0, 0); cp_commit();
    load_async(1, 1); cp_commit();

    const uint32_t aoff = (wm * 64 + (lid & 15)) * RSTR + ((lid >> 4) & 1) * 16;
    const uint32_t boff = (wn * 32 + (lid & 7)) * RSTR + ((lid >> 3) & 1) * 16;

    float4 st[4];

#pragma unroll 1
    for (int c = 0; c < nch; ++c) {
        if (c + 1 < nch) cp_wait<1>(); else cp_wait<0>();
        __syncthreads();

        bool pend_a2 = false;
        const int c2 = c + 2;
        if (c2 < nch) {
            load_async(c2, c2 % 3);
            if (c2 >= 8 && jb.A2f) { ldg_a2(c2, st); pend_a2 = true; }
            cp_commit();
        }

        const uint32_t s0 = sb + (c % 3) * STG_BYTES;
#pragma unroll
        for (int ks = 0; ks < 2; ++ks) {
            const uint32_t kb = ks * 32;   // 16 fp16 = 32B per k-step
            uint32_t b[4][2];
#pragma unroll
            for (int ni = 0; ni < 4; ++ni)
                ldsm2(b[ni], s0 + T_B + boff + ni * 8 * RSTR + kb);
#pragma unroll
            for (int mi = 0; mi < 4; ++mi) {
                uint32_t a[4];
                ldsm4(a, s0 + T_A + aoff + mi * 16 * RSTR + kb);
#pragma unroll
                for (int ni = 0; ni < 4; ++ni)
                    mma16816(acc[mi][ni], a, b[ni]);
            }
        }

        if (pend_a2) sts_a2(c2 % 3, st);
    }

    // Epilogue. D frag: lane holds (row g, col 2tg), (row g+8) pairs.
    const int g = lid >> 2;
    const int tg = lid & 3;
#pragma unroll
    for (int mi = 0; mi < 4; ++mi) {
#pragma unroll
        for (int half = 0; half < 2; ++half) {
            const int rm = m0 + wm * 64 + mi * 16 + g + half * 8;
            if (jb.mode == 0) {
                float* dst = jb.out + (size_t)rm * 256;
#pragma unroll
                for (int ni = 0; ni < 4; ++ni) {
                    const int cn = n0 + wn * 32 + ni * 8 + tg * 2;
                    *(float2*)(dst + cn) = make_float2(acc[mi][ni][half * 2],
                                                       acc[mi][ni][half * 2 + 1]);
                }
            } else if (jb.mode == 1) {
                const int HW = jb.Hc * jb.Wc;
                const int b = rm / HW;
                const int rem = rm - b * HW;
                const int h = rem / jb.Wc;
                const int w = rem - h * jb.Wc;
                const int Wf = jb.Wc * jb.F;
                for (int dy = 0; dy < jb.F; ++dy)
                    for (int dx = 0; dx < jb.F; ++dx) {
                        size_t fm = (size_t)(b * jb.Hc * jb.F + h * jb.F + dy) * Wf
                                    + (w * jb.F + dx);
                        float* dst = jb.out + fm * 256;
#pragma unroll
                        for (int ni = 0; ni < 4; ++ni) {
                            const int cn = n0 + wn * 32 + ni * 8 + tg * 2;
                            *(float2*)(dst + cn) = make_float2(acc[mi][ni][half * 2],
                                                               acc[mi][ni][half * 2 + 1]);
                        }
                    }
            } else {
                const int Wf = jb.Wc * jb.F;
                const int HWf = jb.Hc * jb.F * Wf;
                const int b = rm / HWf;
                const int rem = rm - b * HWf;
                const int h = rem / Wf;
                const int w = rem - h * Wf;
                const int crow = (b * jb.Hc + h / jb.F) * jb.Wc + (w / jb.F);
                const float* csrc = jb.Cadd + (size_t)crow * 256;
                float* dst = jb.out + (size_t)rm * 256;
#pragma unroll
                for (int ni = 0; ni < 4; ++ni) {
                    const int cn = n0 + wn * 32 + ni * 8 + tg * 2;
                    float2 cv = *(const float2*)(csrc + cn);
                    *(float2*)(dst + cn) = make_float2(acc[mi][ni][half * 2] + cv.x,
                                                       acc[mi][ni][half * 2 + 1] + cv.y);
                }
            }
        }
    }
}

// ---------------------------------------------------------------------------
// Launch
// ---------------------------------------------------------------------------
extern "C" void kernel_launch(void* const* d_in, const int* in_sizes, int n_in,
                              void* d_out, int out_size) {
    (void)n_in; (void)out_size;

    const float* x0 = (const float*)d_in[0];   // [8,16,16,256]
    const float* x1 = (const float*)d_in[1];   // [8,32,32,256]
    const float* x2 = (const float*)d_in[2];   // [8,64,64,256]

    // setup_inputs() builds the dict INTERLEAVED (qpeer_w0, kvpeer_w0, ...).
    // Disambiguate by element count: kv = 512*256, q = 256*256.
    const bool inter = (in_sizes[4] == 2 * 256 * 256);
    const float* kvpeer0 = (const float*)d_in[inter ? 4  : 6];
    const float* kvpeer1 = (const float*)d_in[inter ? 6  : 7];
    const float* kvpeer2 = (const float*)d_in[inter ? 8  : 8];
    const float* kvpar1  = (const float*)d_in[inter ? 10 : 11];
    const float* kvpar2  = (const float*)d_in[inter ? 12 : 12];
    const float* kvkid0  = (const float*)d_in[inter ? 14 : 15];
    const float* kvkid1  = (const float*)d_in[inter ? 16 : 16];

    __half *P0, *Pa, *Pb, *W;
    float *C0, *C1;
    cudaGetSymbolAddress((void**)&P0, g_P0);
    cudaGetSymbolAddress((void**)&Pa, g_Pa);
    cudaGetSymbolAddress((void**)&Pb, g_Pb);
    cudaGetSymbolAddress((void**)&W, g_W);
    cudaGetSymbolAddress((void**)&C0, g_C0);
    cudaGetSymbolAddress((void**)&C1, g_C1);

    float* out0 = (float*)d_out;                 // 8*16*16*256
    float* out1 = out0 + 8 * 16 * 16 * 256;      // 8*32*32*256
    float* out2 = out1 + 8 * 32 * 32 * 256;      // 8*64*64*256

    cudaFuncSetAttribute(gemm_tc, cudaFuncAttributeMaxDynamicSharedMemorySize, SMEM_TOTAL);

    // 1) prep: pools + fp16 conversions (weights)
    PrepArgs pa;
    pa.x0 = x0; pa.x1 = x1; pa.x2 = x2;
    pa.w[0] = kvpeer0; pa.w[1] = kvpeer1; pa.w[2] = kvpeer2;
    pa.w[3] = kvpar1;  pa.w[4] = kvpar2;  pa.w[5] = kvkid0;  pa.w[6] = kvkid1;
    prep_kernel<<<(PREP_TOTAL + 255) / 256, 256>>>(pa);

    __half* W0 = W;             // peer0
    __half* W1 = W + 65536;     // peer1
    __half* W2 = W + 131072;    // peer2
    __half* W3 = W + 196608;    // par1
    __half* W4 = W + 262144;    // par2
    __half* W5 = W + 327680;    // kid0
    __half* W6 = W + 393216;    // kid1

    // 2) coarse: C0 = P0@Wp0^T ; C1 = Pa@Wp1^T + x0@Wpar1^T ;
    //    out2 = up2(Pb@Wp2^T + x1@Wpar2^T)
    TCJobs cj;
    cj.njobs = 3;
    cj.j[0] = { P0, W0, nullptr, nullptr, C0,   nullptr, 2,   0,  0,  0, 0 };
    cj.j[1] = { Pa, W1, W3,      x0,      C1,   nullptr, 34,  0,  0,  0, 0 };
    cj.j[2] = { Pb, W2, W4,      x1,      out2, nullptr, 162, 32, 32, 2, 1 };
    gemm_tc<<<162, 256, SMEM_TOTAL>>>(cj);

    // 3) fine: out0 = Pa@Wk0^T + up4(C0) ; out1 = Pb@Wk1^T + up2(C1)
    TCJobs fj;
    fj.njobs = 2;
    fj.j[0] = { Pa, W5, nullptr, nullptr, out0, C0, 32,  4,  4,  4, 2 };
    fj.j[1] = { Pb, W6, nullptr, nullptr, out1, C1, 160, 16, 16, 2, 2 };
    fj.j[2] = fj.j[1];
    gemm_tc<<<160, 256, SMEM_TOTAL>>>(fj);
}

// round 9
// speedup vs baseline: 4.5983x; 1.0487x over previous
#include <cuda_runtime.h>
#include <cuda_fp16.h>
#include <cstdint>

// ---------------------------------------------------------------------------
// MSAttention: einsum 'bkhwlm,bkhwlnf->bkhwlf' factorizes as
// (sum_m A)*(sum_n V) = 1 * sum_n V  =>  attention is dead code. Output is a
// sum of V-projections of (block-sum) pooled inputs:
//   out0 = Wvkid0*pool2(x1) + up4( Wvpeer0*pool4(x0) )
//   out1 = Wvkid1*pool2(x2) + up2( Wvpeer1*pool2(x1) + Wvpar1*x0 )
//   out2 =                    up2( Wvpeer2*pool2(x2) + Wvpar2*x1 )
// Wv* = rows [256,512) of the kv weights.
//
// GEMMs via mma.sync m16n8k16 fp16 / fp32 acc. Operands are pre-staged by
// prep in a CHUNK-PLANAR, PRE-SWIZZLED layout so the GEMM loads each 8KB
// tile with a single cp.async.bulk (sm_90 baseline; tcgen05 is 'a'-gated
// and unavailable under this harness's plain-sm_103 ptxas). This removes
// the LDGSTS issue-rate bottleneck (1024 cp16/chunk -> 2 bulk/chunk).
//
// Layout per staged matrix (R rows, K=256): 8 chunk planes of R*64 bytes.
// Within a plane: row pair rp = r>>1 owns a 128B atom; 16B slot index
//   slot(r,t) = ((r&1)*4 | t) ^ (rp & 7),  t = k16-slot 0..3
// -> conflict-free ldmatrix for both A (m16k16) and B (n8k16) patterns.
// ---------------------------------------------------------------------------

// ---- staged operands ----
__device__ __align__(1024) __half g_P0[128 * 256];
__device__ __align__(1024) __half g_Pa[2048 * 256];
__device__ __align__(1024) __half g_Pb[8192 * 256];
__device__ __align__(1024) __half g_W[7 * 65536];
__device__ float g_C0[128 * 256];
__device__ float g_C1[2048 * 256];

// ---------------------------------------------------------------------------
// PTX helpers (baseline sm_90 features only)
// ---------------------------------------------------------------------------
__device__ __forceinline__ uint32_t smem_to_u32(const void* p) {
    uint32_t a;
    asm("{ .reg .u64 t; cvta.to.shared.u64 t, %1; cvt.u32.u64 %0, t; }" : "=r"(a) : "l"(p));
    return a;
}
__device__ __forceinline__ void bulk_cp(uint32_t smem, const void* gmem, uint32_t bytes,
                                        uint32_t mbar) {
    asm volatile(
        "cp.async.bulk.shared::cluster.global.mbarrier::complete_tx::bytes [%0], [%1], %2, [%3];"
        :: "r"(smem), "l"(gmem), "r"(bytes), "r"(mbar) : "memory");
}
#define MBARRIER_INIT(mbar, cnt) \
    asm volatile("mbarrier.init.shared.b64 [%0], %1;" :: "r"((uint32_t)(mbar)), "r"((uint32_t)(cnt)) : "memory")
#define MBARRIER_EXPECT_TX(mbar, tx) \
    asm volatile("mbarrier.arrive.expect_tx.shared.b64 _, [%0], %1;" :: "r"((uint32_t)(mbar)), "r"((uint32_t)(tx)) : "memory")
#define MBARRIER_WAIT_PARITY(mbar, par) do {                                      \
    uint32_t _m = (uint32_t)(mbar); uint32_t _p = (uint32_t)(par); uint32_t _d;   \
    asm volatile("{\n\t.reg .pred p;\n\t"                                         \
        "mbarrier.try_wait.parity.acquire.cta.shared::cta.b64 p, [%1], %2;\n\t"   \
        "selp.b32 %0, 1, 0, p;\n\t}" : "=r"(_d) : "r"(_m), "r"(_p) : "memory");   \
    if (!_d) {                                                                     \
        asm volatile("{\n\t.reg .pred P1;\n\t"                                    \
            "WL_%=:\n\t"                                                          \
            "mbarrier.try_wait.parity.acquire.cta.shared::cta.b64 P1, [%0], %1, 0x989680;\n\t" \
            "@P1 bra.uni WD_%=;\n\t"                                              \
            "bra.uni WL_%=;\n\t"                                                  \
            "WD_%=:\n\t}" :: "r"(_m), "r"(_p) : "memory");                        \
    }                                                                              \
} while (0)

__device__ __forceinline__ void ldsm4(uint32_t* r, uint32_t addr) {
    asm volatile("ldmatrix.sync.aligned.m8n8.x4.shared.b16 {%0,%1,%2,%3}, [%4];"
                 : "=r"(r[0]), "=r"(r[1]), "=r"(r[2]), "=r"(r[3]) : "r"(addr));
}
__device__ __forceinline__ void ldsm2(uint32_t* r, uint32_t addr) {
    asm volatile("ldmatrix.sync.aligned.m8n8.x2.shared.b16 {%0,%1}, [%2];"
                 : "=r"(r[0]), "=r"(r[1]) : "r"(addr));
}
__device__ __forceinline__ void mma16816(float* d, const uint32_t* a, const uint32_t* b) {
    asm volatile(
        "mma.sync.aligned.m16n8k16.row.col.f32.f16.f16.f32 "
        "{%0,%1,%2,%3}, {%4,%5,%6,%7}, {%8,%9}, {%0,%1,%2,%3};"
        : "+f"(d[0]), "+f"(d[1]), "+f"(d[2]), "+f"(d[3])
        : "r"(a[0]), "r"(a[1]), "r"(a[2]), "r"(a[3]), "r"(b[0]), "r"(b[1]));
}
__device__ __forceinline__ void sts128(uint32_t addr, uint4 v) {
    asm volatile("st.shared.v4.b32 [%0], {%1,%2,%3,%4};"
                 :: "r"(addr), "r"(v.x), "r"(v.y), "r"(v.z), "r"(v.w) : "memory");
}

// slot byte-offset inside a chunk plane for (row r, 16B-slot t)
__device__ __forceinline__ uint32_t plane_off(int r, int t) {
    return (uint32_t)((r >> 1) * 128 + (((((r & 1) << 2) | t) ^ ((r >> 1) & 7)) << 4));
}

// ---------------------------------------------------------------------------
// Prep: pools + fp32->fp16, written chunk-planar pre-swizzled.
// Slot ordering per job: [chunk c][row r][slot t]  (warp = 8 rows x 4 slots
// of one chunk -> fully covered 128B atoms, coalesced stores).
// ---------------------------------------------------------------------------
#define S0 (128 * 32)      // P0 slots
#define S1 (2048 * 32)     // Pa
#define S2 (8192 * 32)     // Pb
#define SW (7 * 256 * 32)  // weights
#define PREP_TOTAL (S0 + S1 + S2 + SW)

struct PrepArgs {
    const float* x0; const float* x1; const float* x2;
    const float* w[7];
};

__device__ __forceinline__ float4 pool4f(const float* in, int i, int Hc, int f) {
    int Wc = Hc;
    int c4 = i & 63;
    int r = i >> 6;
    int q = r % Wc; r /= Wc;
    int p = r % Hc;
    int b = r / Hc;
    int Win = Wc * f;
    const float4* in4 = (const float4*)in;
    float4 s = make_float4(0.f, 0.f, 0.f, 0.f);
    for (int dy = 0; dy < f; ++dy)
        for (int dx = 0; dx < f; ++dx) {
            float4 v = in4[(size_t)((b * Hc * f + p * f + dy) * Win + q * f + dx) * 64 + c4];
            s.x += v.x; s.y += v.y; s.z += v.z; s.w += v.w;
        }
    return s;
}

__device__ __forceinline__ uint4 pack8(float4 a, float4 b) {
    __half2 h0 = __floats2half2_rn(a.x, a.y);
    __half2 h1 = __floats2half2_rn(a.z, a.w);
    __half2 h2 = __floats2half2_rn(b.x, b.y);
    __half2 h3 = __floats2half2_rn(b.z, b.w);
    uint4 u;
    u.x = *(uint32_t*)&h0; u.y = *(uint32_t*)&h1;
    u.z = *(uint32_t*)&h2; u.w = *(uint32_t*)&h3;
    return u;
}

__device__ __forceinline__ void prep_pool(const float* in, __half* dst, int R, int Hc,
                                          int f, int i) {
    const int t = i & 3;
    const int r = (i >> 2) % R;
    const int c = (i >> 2) / R;
    const int c4 = c * 8 + t * 2;
    float4 v0 = pool4f(in, r * 64 + c4, Hc, f);
    float4 v1 = pool4f(in, r * 64 + c4 + 1, Hc, f);
    __half* p = dst + (size_t)c * R * 32 + (plane_off(r, t) >> 1);
    *(uint4*)p = pack8(v0, v1);
}

__global__ void prep_kernel(PrepArgs pa) {
    int i = blockIdx.x * blockDim.x + threadIdx.x;
    const int VOFF = 256 * 256;
    if (i < S0) {
        prep_pool(pa.x0, g_P0, 128, 4, 4, i);
    } else if ((i -= S0) < S1) {
        prep_pool(pa.x1, g_Pa, 2048, 16, 2, i);
    } else if ((i -= S1) < S2) {
        prep_pool(pa.x2, g_Pb, 8192, 32, 2, i);
    } else if ((i -= S2) < SW) {
        const int mat = i >> 13;          // 256*32 slots per matrix
        const int rem = i & 8191;
        const int c = rem >> 10;          // 256*4
        const int r = (rem >> 2) & 255;
        const int t = rem & 3;
        const float* src = pa.w[mat] + VOFF + r * 256 + c * 32 + t * 8;
        float4 v0 = ((const float4*)src)[0];
        float4 v1 = ((const float4*)src)[1];
        __half* p = g_W + ((size_t)mat << 16) + (size_t)c * 256 * 32 + (plane_off(r, t) >> 1);
        *(uint4*)p = pack8(v0, v1);
    }
}

// ---------------------------------------------------------------------------
// GEMM: BM=128, BN=128, BK=32, 8 warps, 4-stage bulk-copy mbarrier pipeline.
// K=512 jobs: chunks 8..15 take A from fp32 gmem (A2f) via LDG+swizzled STS.
// mode 0: plain store; 1: scatter-up by F; 2: gather-add Cadd[coarse(m)].
// ---------------------------------------------------------------------------
struct TCJob {
    const __half *A1, *W1, *W2;
    const float* A2f;
    float* out;
    const float* Cadd;
    int aplane;   // bytes per A chunk plane (= R*64)
    int tile_end, Hc, Wc, F, mode;
};
struct TCJobs { TCJob j[3]; int njobs; };

#define STG 16384                  // stage bytes: A 8KB + B 8KB
#define SMEM_TOTAL (4 * STG)       // 65536

__global__ void __launch_bounds__(256, 2)
gemm_tc(TCJobs jobs) {
    extern __shared__ char smem[];
    __shared__ __align__(8) unsigned long long mbars[4];
    const uint32_t sb = smem_to_u32(smem);
    const uint32_t mb = smem_to_u32(mbars);
    const int tid = threadIdx.x;
    const int lid = tid & 31;
    const int wid = tid >> 5;
    const int wm = wid >> 2;       // 0..1
    const int wn = wid & 3;        // 0..3

    const int bt = blockIdx.x;
    int ji = 0;
    if (jobs.njobs > 1 && bt >= jobs.j[0].tile_end) ji = 1;
    if (jobs.njobs > 2 && bt >= jobs.j[1].tile_end) ji = 2;
    const TCJob jb = jobs.j[ji];
    const int local = bt - (ji == 0 ? 0 : jobs.j[ji - 1].tile_end);
    const int m0 = (local >> 1) * 128;
    const int n0 = (local & 1) * 128;

    const int nch = jb.W2 ? 16 : 8;

    float acc[4][4][4];
#pragma unroll
    for (int a = 0; a < 4; ++a)
#pragma unroll
        for (int b = 0; b < 4; ++b)
#pragma unroll
            for (int c = 0; c < 4; ++c) acc[a][b][c] = 0.f;

    if (tid == 0) {
#pragma unroll
        for (int s = 0; s < 4; ++s) MBARRIER_INIT(mb + 8 * s, 1);
    }
    __syncthreads();

    // issue chunk c into stage c%4 (B always bulk; A bulk only for c<8)
    auto issue = [&](int c) {
        const int s = c & 3;
        const uint32_t stg = sb + s * STG;
        const bool bulkA = (c < 8);
        MBARRIER_EXPECT_TX(mb + 8 * s, bulkA ? 16384u : 8192u);
        const char* wsrc = (const char*)((c < 8) ? jb.W1 : jb.W2) + (c & 7) * 16384 + n0 * 64;
        bulk_cp(stg + 8192, wsrc, 8192, mb + 8 * s);
        if (bulkA) {
            const char* asrc = (const char*)jb.A1 + (size_t)c * jb.aplane + (size_t)m0 * 64;
            bulk_cp(stg, asrc, 8192, mb + 8 * s);
        }
    };

    if (tid == 0) { issue(0); issue(1); issue(2); }

    // per-thread ldmatrix address precompute
    const int rA0 = wm * 64 + (lid & 15);
    const int hiA = lid >> 4;
    const uint32_t aBase = (rA0 >> 1) * 128;
    const int xvA = (rA0 >> 1) & 7;
    const int pbA = (rA0 & 1) << 2;
    const uint32_t soA0 = (uint32_t)(((pbA | hiA) ^ xvA) << 4);
    const uint32_t soA1 = (uint32_t)(((pbA | (2 + hiA)) ^ xvA) << 4);

    const int l16 = lid & 15;
    const int rB0 = wn * 32 + (l16 & 7);
    const int hiB = l16 >> 3;
    const uint32_t bBase = (rB0 >> 1) * 128;
    const int xvB = (rB0 >> 1) & 7;
    const int pbB = (rB0 & 1) << 2;
    const uint32_t soB00 = (uint32_t)(((pbB | hiB) ^ xvB) << 4);
    const uint32_t soB01 = (uint32_t)(((pbB | hiB) ^ xvB ^ 4) << 4);
    const uint32_t soB10 = (uint32_t)(((pbB | (2 + hiB)) ^ xvB) << 4);
    const uint32_t soB11 = (uint32_t)(((pbB | (2 + hiB)) ^ xvB ^ 4) << 4);

    // fp32 A path indices (thread covers one row, two 16B slots)
    const int fr = tid >> 1;
    const int ft = (tid & 1) * 2;

    float4 st[4];

#pragma unroll 1
    for (int c = 0; c < nch; ++c) {
        const int s = c & 3;
        MBARRIER_WAIT_PARITY(mb + 8 * s, (c >> 2) & 1);

        const int c3 = c + 3;
        const bool ld2 = (c3 < nch) && (c3 >= 8);
        if (ld2) {
            const float* g = jb.A2f + (size_t)(m0 + fr) * 256 + (c3 & 7) * 32 + ft * 8;
            st[0] = ((const float4*)g)[0];
            st[1] = ((const float4*)g)[1];
            st[2] = ((const float4*)g)[2];
            st[3] = ((const float4*)g)[3];
        }

        const uint32_t sA = sb + s * STG;
        const uint32_t sB = sA + 8192;
#pragma unroll
        for (int ks = 0; ks < 2; ++ks) {
            uint32_t b[4][2];
            const uint32_t sbk0 = ks ? soB10 : soB00;
            const uint32_t sbk1 = ks ? soB11 : soB01;
#pragma unroll
            for (int ni = 0; ni < 4; ++ni)
                ldsm2(b[ni], sB + bBase + ni * 512 + ((ni & 1) ? sbk1 : sbk0));
            const uint32_t sak = ks ? soA1 : soA0;
#pragma unroll
            for (int mi = 0; mi < 4; ++mi) {
                uint32_t a[4];
                ldsm4(a, sA + aBase + mi * 1024 + sak);
#pragma unroll
                for (int ni = 0; ni < 4; ++ni)
                    mma16816(acc[mi][ni], a, b[ni]);
            }
        }

        if (ld2) {
            const uint32_t stg = sb + (c3 & 3) * STG + (fr >> 1) * 128;
            const int pb = (fr & 1) << 2;
            const int xv = (fr >> 1) & 7;
            sts128(stg + (((pb | ft) ^ xv) << 4), pack8(st[0], st[1]));
            sts128(stg + (((pb | (ft + 1)) ^ xv) << 4), pack8(st[2], st[3]));
        }
        __syncthreads();
        if (c3 < nch && tid == 0) issue(c3);
    }

    // Epilogue. D frag: lane holds (row g, col 2tg), (row g+8) pairs.
    const int g = lid >> 2;
    const int tg = lid & 3;
#pragma unroll
    for (int mi = 0; mi < 4; ++mi) {
#pragma unroll
        for (int half = 0; half < 2; ++half) {
            const int rm = m0 + wm * 64 + mi * 16 + g + half * 8;
            if (jb.mode == 0) {
                float* dst = jb.out + (size_t)rm * 256;
#pragma unroll
                for (int ni = 0; ni < 4; ++ni) {
                    const int cn = n0 + wn * 32 + ni * 8 + tg * 2;
                    *(float2*)(dst + cn) = make_float2(acc[mi][ni][half * 2],
                                                       acc[mi][ni][half * 2 + 1]);
                }
            } else if (jb.mode == 1) {
                const int HW = jb.Hc * jb.Wc;
                const int b = rm / HW;
                const int rem = rm - b * HW;
                const int h = rem / jb.Wc;
                const int w = rem - h * jb.Wc;
                const int Wf = jb.Wc * jb.F;
                for (int dy = 0; dy < jb.F; ++dy)
                    for (int dx = 0; dx < jb.F; ++dx) {
                        size_t fm = (size_t)(b * jb.Hc * jb.F + h * jb.F + dy) * Wf
                                    + (w * jb.F + dx);
                        float* dst = jb.out + fm * 256;
#pragma unroll
                        for (int ni = 0; ni < 4; ++ni) {
                            const int cn = n0 + wn * 32 + ni * 8 + tg * 2;
                            *(float2*)(dst + cn) = make_float2(acc[mi][ni][half * 2],
                                                               acc[mi][ni][half * 2 + 1]);
                        }
                    }
            } else {
                const int Wf = jb.Wc * jb.F;
                const int HWf = jb.Hc * jb.F * Wf;
                const int b = rm / HWf;
                const int rem = rm - b * HWf;
                const int h = rem / Wf;
                const int w = rem - h * Wf;
                const int crow = (b * jb.Hc + h / jb.F) * jb.Wc + (w / jb.F);
                const float* csrc = jb.Cadd + (size_t)crow * 256;
                float* dst = jb.out + (size_t)rm * 256;
#pragma unroll
                for (int ni = 0; ni < 4; ++ni) {
                    const int cn = n0 + wn * 32 + ni * 8 + tg * 2;
                    float2 cv = *(const float2*)(csrc + cn);
                    *(float2*)(dst + cn) = make_float2(acc[mi][ni][half * 2] + cv.x,
                                                       acc[mi][ni][half * 2 + 1] + cv.y);
                }
            }
        }
    }
}

// ---------------------------------------------------------------------------
// Launch
// ---------------------------------------------------------------------------
extern "C" void kernel_launch(void* const* d_in, const int* in_sizes, int n_in,
                              void* d_out, int out_size) {
    (void)n_in; (void)out_size;

    const float* x0 = (const float*)d_in[0];   // [8,16,16,256]
    const float* x1 = (const float*)d_in[1];   // [8,32,32,256]
    const float* x2 = (const float*)d_in[2];   // [8,64,64,256]

    // setup_inputs() builds the dict INTERLEAVED (qpeer_w0, kvpeer_w0, ...).
    const bool inter = (in_sizes[4] == 2 * 256 * 256);
    const float* kvpeer0 = (const float*)d_in[inter ? 4  : 6];
    const float* kvpeer1 = (const float*)d_in[inter ? 6  : 7];
    const float* kvpeer2 = (const float*)d_in[inter ? 8  : 8];
    const float* kvpar1  = (const float*)d_in[inter ? 10 : 11];
    const float* kvpar2  = (const float*)d_in[inter ? 12 : 12];
    const float* kvkid0  = (const float*)d_in[inter ? 14 : 15];
    const float* kvkid1  = (const float*)d_in[inter ? 16 : 16];

    __half *P0, *Pa, *Pb, *W;
    float *C0, *C1;
    cudaGetSymbolAddress((void**)&P0, g_P0);
    cudaGetSymbolAddress((void**)&Pa, g_Pa);
    cudaGetSymbolAddress((void**)&Pb, g_Pb);
    cudaGetSymbolAddress((void**)&W, g_W);
    cudaGetSymbolAddress((void**)&C0, g_C0);
    cudaGetSymbolAddress((void**)&C1, g_C1);

    float* out0 = (float*)d_out;                 // 8*16*16*256
    float* out1 = out0 + 8 * 16 * 16 * 256;      // 8*32*32*256
    float* out2 = out1 + 8 * 32 * 32 * 256;      // 8*64*64*256

    cudaFuncSetAttribute(gemm_tc, cudaFuncAttributeMaxDynamicSharedMemorySize, SMEM_TOTAL);

    // 1) prep
    PrepArgs pa;
    pa.x0 = x0; pa.x1 = x1; pa.x2 = x2;
    pa.w[0] = kvpeer0; pa.w[1] = kvpeer1; pa.w[2] = kvpeer2;
    pa.w[3] = kvpar1;  pa.w[4] = kvpar2;  pa.w[5] = kvkid0;  pa.w[6] = kvkid1;
    prep_kernel<<<(PREP_TOTAL + 255) / 256, 256>>>(pa);

    __half* W0 = W;             // peer0
    __half* W1 = W + 65536;     // peer1
    __half* W2 = W + 131072;    // peer2
    __half* W3 = W + 196608;    // par1
    __half* W4 = W + 262144;    // par2
    __half* W5 = W + 327680;    // kid0
    __half* W6 = W + 393216;    // kid1

    // 2) coarse: C0 = P0@Wp0^T ; C1 = Pa@Wp1^T + x0@Wpar1^T ;
    //    out2 = up2(Pb@Wp2^T + x1@Wpar2^T)
    TCJobs cj;
    cj.njobs = 3;
    cj.j[0] = { P0, W0, nullptr, nullptr, C0,   nullptr, 128 * 64,  2,   0,  0,  0, 0 };
    cj.j[1] = { Pa, W1, W3,      x0,      C1,   nullptr, 2048 * 64, 34,  0,  0,  0, 0 };
    cj.j[2] = { Pb, W2, W4,      x1,      out2, nullptr, 8192 * 64, 162, 32, 32, 2, 1 };
    gemm_tc<<<162, 256, SMEM_TOTAL>>>(cj);

    // 3) fine: out0 = Pa@Wk0^T + up4(C0) ; out1 = Pb@Wk1^T + up2(C1)
    TCJobs fj;
    fj.njobs = 2;
    fj.j[0] = { Pa, W5, nullptr, nullptr, out0, C0, 2048 * 64, 32,  4,  4,  4, 2 };
    fj.j[1] = { Pb, W6, nullptr, nullptr, out1, C1, 8192 * 64, 160, 16, 16, 2, 2 };
    fj.j[2] = fj.j[1];
    gemm_tc<<<160, 256, SMEM_TOTAL>>>(fj);
}

// round 10
// speedup vs baseline: 5.7358x; 1.2474x over previous
#include <cuda_runtime.h>
#include <cuda_fp16.h>
#include <cstdint>

// ---------------------------------------------------------------------------
// MSAttention: einsum 'bkhwlm,bkhwlnf->bkhwlf' factorizes as
// (sum_m A)*(sum_n V) = 1 * sum_n V  =>  attention is dead code. Output is a
// sum of V-projections of (block-sum) pooled inputs:
//   out0 = Wvkid0*pool2(x1) + up4( Wvpeer0*pool4(x0) )
//   out1 = Wvkid1*pool2(x2) + up2( Wvpeer1*pool2(x1) + Wvpar1*x0 )
//   out2 =                    up2( Wvpeer2*pool2(x2) + Wvpar2*x1 )
// Wv* = rows [256,512) of the kv weights.
//
// GEMMs via mma.sync m16n8k16 fp16 / fp32 acc, operands pre-staged
// chunk-planar + pre-swizzled so each 8KB tile loads with one cp.async.bulk.
// ALL GEMM tiles run in ONE launch: the 34 CTAs producing C0/C1 signal a
// device counter; consumer CTAs run their full mainloop first and spin on
// the counter only before their gather-add epilogue (producers are blocks
// 0..33 -> always wave-1 resident -> no deadlock).
// ---------------------------------------------------------------------------

// ---- staged operands ----
__device__ __align__(1024) __half g_P0[128 * 256];
__device__ __align__(1024) __half g_Pa[2048 * 256];
__device__ __align__(1024) __half g_Pb[8192 * 256];
__device__ __align__(1024) __half g_W[7 * 65536];
__device__ float g_C0[128 * 256];
__device__ float g_C1[2048 * 256];
__device__ int g_done;

// ---------------------------------------------------------------------------
// PTX helpers (baseline sm_90 features only)
// ---------------------------------------------------------------------------
__device__ __forceinline__ uint32_t smem_to_u32(const void* p) {
    uint32_t a;
    asm("{ .reg .u64 t; cvta.to.shared.u64 t, %1; cvt.u32.u64 %0, t; }" : "=r"(a) : "l"(p));
    return a;
}
__device__ __forceinline__ void bulk_cp(uint32_t smem, const void* gmem, uint32_t bytes,
                                        uint32_t mbar) {
    asm volatile(
        "cp.async.bulk.shared::cluster.global.mbarrier::complete_tx::bytes [%0], [%1], %2, [%3];"
        :: "r"(smem), "l"(gmem), "r"(bytes), "r"(mbar) : "memory");
}
#define MBARRIER_INIT(mbar, cnt) \
    asm volatile("mbarrier.init.shared.b64 [%0], %1;" :: "r"((uint32_t)(mbar)), "r"((uint32_t)(cnt)) : "memory")
#define MBARRIER_EXPECT_TX(mbar, tx) \
    asm volatile("mbarrier.arrive.expect_tx.shared.b64 _, [%0], %1;" :: "r"((uint32_t)(mbar)), "r"((uint32_t)(tx)) : "memory")
#define MBARRIER_WAIT_PARITY(mbar, par) do {                                      \
    uint32_t _m = (uint32_t)(mbar); uint32_t _p = (uint32_t)(par); uint32_t _d;   \
    asm volatile("{\n\t.reg .pred p;\n\t"                                         \
        "mbarrier.try_wait.parity.acquire.cta.shared::cta.b64 p, [%1], %2;\n\t"   \
        "selp.b32 %0, 1, 0, p;\n\t}" : "=r"(_d) : "r"(_m), "r"(_p) : "memory");   \
    if (!_d) {                                                                     \
        asm volatile("{\n\t.reg .pred P1;\n\t"                                    \
            "WL_%=:\n\t"                                                          \
            "mbarrier.try_wait.parity.acquire.cta.shared::cta.b64 P1, [%0], %1, 0x989680;\n\t" \
            "@P1 bra.uni WD_%=;\n\t"                                              \
            "bra.uni WL_%=;\n\t"                                                  \
            "WD_%=:\n\t}" :: "r"(_m), "r"(_p) : "memory");                        \
    }                                                                              \
} while (0)

__device__ __forceinline__ void ldsm4(uint32_t* r, uint32_t addr) {
    asm volatile("ldmatrix.sync.aligned.m8n8.x4.shared.b16 {%0,%1,%2,%3}, [%4];"
                 : "=r"(r[0]), "=r"(r[1]), "=r"(r[2]), "=r"(r[3]) : "r"(addr));
}
__device__ __forceinline__ void ldsm2(uint32_t* r, uint32_t addr) {
    asm volatile("ldmatrix.sync.aligned.m8n8.x2.shared.b16 {%0,%1}, [%2];"
                 : "=r"(r[0]), "=r"(r[1]) : "r"(addr));
}
__device__ __forceinline__ void mma16816(float* d, const uint32_t* a, const uint32_t* b) {
    asm volatile(
        "mma.sync.aligned.m16n8k16.row.col.f32.f16.f16.f32 "
        "{%0,%1,%2,%3}, {%4,%5,%6,%7}, {%8,%9}, {%0,%1,%2,%3};"
        : "+f"(d[0]), "+f"(d[1]), "+f"(d[2]), "+f"(d[3])
        : "r"(a[0]), "r"(a[1]), "r"(a[2]), "r"(a[3]), "r"(b[0]), "r"(b[1]));
}
__device__ __forceinline__ void sts128(uint32_t addr, uint4 v) {
    asm volatile("st.shared.v4.b32 [%0], {%1,%2,%3,%4};"
                 :: "r"(addr), "r"(v.x), "r"(v.y), "r"(v.z), "r"(v.w) : "memory");
}

// slot byte-offset inside a chunk plane for (row r, 16B-slot t)
__device__ __forceinline__ uint32_t plane_off(int r, int t) {
    return (uint32_t)((r >> 1) * 128 + (((((r & 1) << 2) | t) ^ ((r >> 1) & 7)) << 4));
}

// ---------------------------------------------------------------------------
// Prep: pools + fp32->fp16, written chunk-planar pre-swizzled.
// ---------------------------------------------------------------------------
#define S0 (128 * 32)      // P0 slots
#define S1 (2048 * 32)     // Pa
#define S2 (8192 * 32)     // Pb
#define SW (7 * 256 * 32)  // weights
#define PREP_TOTAL (S0 + S1 + S2 + SW)

struct PrepArgs {
    const float* x0; const float* x1; const float* x2;
    const float* w[7];
};

__device__ __forceinline__ uint4 pack8(float4 a, float4 b) {
    __half2 h0 = __floats2half2_rn(a.x, a.y);
    __half2 h1 = __floats2half2_rn(a.z, a.w);
    __half2 h2 = __floats2half2_rn(b.x, b.y);
    __half2 h3 = __floats2half2_rn(b.z, b.w);
    uint4 u;
    u.x = *(uint32_t*)&h0; u.y = *(uint32_t*)&h1;
    u.z = *(uint32_t*)&h2; u.w = *(uint32_t*)&h3;
    return u;
}

__device__ __forceinline__ void prep_pool(const float* in, __half* dst, int R, int Hc,
                                          int f, int i) {
    const int t = i & 3;
    const int r = (i >> 2) % R;
    const int c = (i >> 2) / R;
    // decode spatial position once (Wc == Hc)
    int q = r % Hc;
    int tmp = r / Hc;
    int p = tmp % Hc;
    int b = tmp / Hc;
    const int c8 = c * 8 + t * 2;   // float4 channel index (two adjacent)
    const int Win = Hc * f;
    const float4* in4 = (const float4*)in;
    float4 s0 = make_float4(0.f, 0.f, 0.f, 0.f);
    float4 s1 = make_float4(0.f, 0.f, 0.f, 0.f);
    for (int dy = 0; dy < f; ++dy)
        for (int dx = 0; dx < f; ++dx) {
            const float4* pp = &in4[(size_t)((b * Hc * f + p * f + dy) * Win + q * f + dx) * 64 + c8];
            float4 v0 = pp[0], v1 = pp[1];
            s0.x += v0.x; s0.y += v0.y; s0.z += v0.z; s0.w += v0.w;
            s1.x += v1.x; s1.y += v1.y; s1.z += v1.z; s1.w += v1.w;
        }
    __half* d = dst + (size_t)c * R * 32 + (plane_off(r, t) >> 1);
    *(uint4*)d = pack8(s0, s1);
}

__global__ void prep_kernel(PrepArgs pa) {
    if (blockIdx.x == 0 && threadIdx.x == 0) g_done = 0;
    int i = blockIdx.x * blockDim.x + threadIdx.x;
    const int VOFF = 256 * 256;
    if (i < S0) {
        prep_pool(pa.x0, g_P0, 128, 4, 4, i);
    } else if ((i -= S0) < S1) {
        prep_pool(pa.x1, g_Pa, 2048, 16, 2, i);
    } else if ((i -= S1) < S2) {
        prep_pool(pa.x2, g_Pb, 8192, 32, 2, i);
    } else if ((i -= S2) < SW) {
        const int mat = i >> 13;          // 256*32 slots per matrix
        const int rem = i & 8191;
        const int c = rem >> 10;          // 256*4
        const int r = (rem >> 2) & 255;
        const int t = rem & 3;
        const float* src = pa.w[mat] + VOFF + r * 256 + c * 32 + t * 8;
        float4 v0 = ((const float4*)src)[0];
        float4 v1 = ((const float4*)src)[1];
        __half* p = g_W + ((size_t)mat << 16) + (size_t)c * 256 * 32 + (plane_off(r, t) >> 1);
        *(uint4*)p = pack8(v0, v1);
    }
}

// ---------------------------------------------------------------------------
// GEMM: BM=128, BN=128, BK=32, 8 warps, 4-stage bulk-copy mbarrier pipeline.
// K=512 jobs: chunks 8..15 take A from fp32 gmem (A2f) via LDG+swizzled STS.
// mode 0: plain store; 1: scatter-up by F; 2: gather-add Cadd[coarse(m)].
// dep  0: none; 1: producer (signal g_done); 2: consumer (wait g_done==nprod
//         before the epilogue; mainloop runs first).
// ---------------------------------------------------------------------------
struct TCJob {
    const __half *A1, *W1, *W2;
    const float* A2f;
    float* out;
    const float* Cadd;
    int aplane;   // bytes per A chunk plane (= R*64)
    int tile_end, Hc, Wc, F, mode, dep;
};
struct TCJobs { TCJob j[5]; int njobs; int nprod; };

#define STG 16384                  // stage bytes: A 8KB + B 8KB
#define SMEM_TOTAL (4 * STG)       // 65536

__global__ void __launch_bounds__(256, 2)
gemm_tc(TCJobs jobs) {
    extern __shared__ char smem[];
    __shared__ __align__(8) unsigned long long mbars[4];
    const uint32_t sb = smem_to_u32(smem);
    const uint32_t mb = smem_to_u32(mbars);
    const int tid = threadIdx.x;
    const int lid = tid & 31;
    const int wid = tid >> 5;
    const int wm = wid >> 2;       // 0..1
    const int wn = wid & 3;        // 0..3

    const int bt = blockIdx.x;
    int ji = 0;
#pragma unroll
    for (int t = 0; t < 4; ++t)
        if (t + 1 < jobs.njobs && bt >= jobs.j[t].tile_end) ji = t + 1;
    const TCJob jb = jobs.j[ji];
    const int local = bt - (ji == 0 ? 0 : jobs.j[ji - 1].tile_end);
    const int m0 = (local >> 1) * 128;
    const int n0 = (local & 1) * 128;

    const int nch = jb.W2 ? 16 : 8;

    float acc[4][4][4];
#pragma unroll
    for (int a = 0; a < 4; ++a)
#pragma unroll
        for (int b = 0; b < 4; ++b)
#pragma unroll
            for (int c = 0; c < 4; ++c) acc[a][b][c] = 0.f;

    if (tid == 0) {
#pragma unroll
        for (int s = 0; s < 4; ++s) MBARRIER_INIT(mb + 8 * s, 1);
    }
    __syncthreads();

    // issue chunk c into stage c%4 (B always bulk; A bulk only for c<8)
    auto issue = [&](int c) {
        const int s = c & 3;
        const uint32_t stg = sb + s * STG;
        const bool bulkA = (c < 8);
        MBARRIER_EXPECT_TX(mb + 8 * s, bulkA ? 16384u : 8192u);
        const char* wsrc = (const char*)((c < 8) ? jb.W1 : jb.W2) + (c & 7) * 16384 + n0 * 64;
        bulk_cp(stg + 8192, wsrc, 8192, mb + 8 * s);
        if (bulkA) {
            const char* asrc = (const char*)jb.A1 + (size_t)c * jb.aplane + (size_t)m0 * 64;
            bulk_cp(stg, asrc, 8192, mb + 8 * s);
        }
    };

    if (tid == 0) { issue(0); issue(1); issue(2); }

    // per-thread ldmatrix address precompute
    const int rA0 = wm * 64 + (lid & 15);
    const int hiA = lid >> 4;
    const uint32_t aBase = (rA0 >> 1) * 128;
    const int xvA = (rA0 >> 1) & 7;
    const int pbA = (rA0 & 1) << 2;
    const uint32_t soA0 = (uint32_t)(((pbA | hiA) ^ xvA) << 4);
    const uint32_t soA1 = (uint32_t)(((pbA | (2 + hiA)) ^ xvA) << 4);

    const int l16 = lid & 15;
    const int rB0 = wn * 32 + (l16 & 7);
    const int hiB = l16 >> 3;
    const uint32_t bBase = (rB0 >> 1) * 128;
    const int xvB = (rB0 >> 1) & 7;
    const int pbB = (rB0 & 1) << 2;
    const uint32_t soB00 = (uint32_t)(((pbB | hiB) ^ xvB) << 4);
    const uint32_t soB01 = (uint32_t)(((pbB | hiB) ^ xvB ^ 4) << 4);
    const uint32_t soB10 = (uint32_t)(((pbB | (2 + hiB)) ^ xvB) << 4);
    const uint32_t soB11 = (uint32_t)(((pbB | (2 + hiB)) ^ xvB ^ 4) << 4);

    // fp32 A path indices (thread covers one row, two 16B slots)
    const int fr = tid >> 1;
    const int ft = (tid & 1) * 2;

    float4 st[4];

#pragma unroll 1
    for (int c = 0; c < nch; ++c) {
        const int s = c & 3;
        MBARRIER_WAIT_PARITY(mb + 8 * s, (c >> 2) & 1);

        const int c3 = c + 3;
        const bool ld2 = (c3 < nch) && (c3 >= 8);
        if (ld2) {
            const float* g = jb.A2f + (size_t)(m0 + fr) * 256 + (c3 & 7) * 32 + ft * 8;
            st[0] = ((const float4*)g)[0];
            st[1] = ((const float4*)g)[1];
            st[2] = ((const float4*)g)[2];
            st[3] = ((const float4*)g)[3];
        }

        const uint32_t sA = sb + s * STG;
        const uint32_t sB = sA + 8192;
#pragma unroll
        for (int ks = 0; ks < 2; ++ks) {
            uint32_t b[4][2];
            const uint32_t sbk0 = ks ? soB10 : soB00;
            const uint32_t sbk1 = ks ? soB11 : soB01;
#pragma unroll
            for (int ni = 0; ni < 4; ++ni)
                ldsm2(b[ni], sB + bBase + ni * 512 + ((ni & 1) ? sbk1 : sbk0));
            const uint32_t sak = ks ? soA1 : soA0;
#pragma unroll
            for (int mi = 0; mi < 4; ++mi) {
                uint32_t a[4];
                ldsm4(a, sA + aBase + mi * 1024 + sak);
#pragma unroll
                for (int ni = 0; ni < 4; ++ni)
                    mma16816(acc[mi][ni], a, b[ni]);
            }
        }

        if (ld2) {
            const uint32_t stg = sb + (c3 & 3) * STG + (fr >> 1) * 128;
            const int pb = (fr & 1) << 2;
            const int xv = (fr >> 1) & 7;
            sts128(stg + (((pb | ft) ^ xv) << 4), pack8(st[0], st[1]));
            sts128(stg + (((pb | (ft + 1)) ^ xv) << 4), pack8(st[2], st[3]));
        }
        __syncthreads();
        if (c3 < nch && tid == 0) issue(c3);
    }

    // Consumers: wait for all C producers before the gather-add epilogue.
    if (jb.dep == 2) {
        if (tid == 0) {
            while (atomicAdd(&g_done, 0) < jobs.nprod) { }
        }
        __syncthreads();
    }

    // Epilogue. D frag: lane holds (row g, col 2tg), (row g+8) pairs.
    const int g = lid >> 2;
    const int tg = lid & 3;
#pragma unroll
    for (int mi = 0; mi < 4; ++mi) {
#pragma unroll
        for (int half = 0; half < 2; ++half) {
            const int rm = m0 + wm * 64 + mi * 16 + g + half * 8;
            if (jb.mode == 0) {
                float* dst = jb.out + (size_t)rm * 256;
#pragma unroll
                for (int ni = 0; ni < 4; ++ni) {
                    const int cn = n0 + wn * 32 + ni * 8 + tg * 2;
                    *(float2*)(dst + cn) = make_float2(acc[mi][ni][half * 2],
                                                       acc[mi][ni][half * 2 + 1]);
                }
            } else if (jb.mode == 1) {
                const int HW = jb.Hc * jb.Wc;
                const int b = rm / HW;
                const int rem = rm - b * HW;
                const int h = rem / jb.Wc;
                const int w = rem - h * jb.Wc;
                const int Wf = jb.Wc * jb.F;
                for (int dy = 0; dy < jb.F; ++dy)
                    for (int dx = 0; dx < jb.F; ++dx) {
                        size_t fm = (size_t)(b * jb.Hc * jb.F + h * jb.F + dy) * Wf
                                    + (w * jb.F + dx);
                        float* dst = jb.out + fm * 256;
#pragma unroll
                        for (int ni = 0; ni < 4; ++ni) {
                            const int cn = n0 + wn * 32 + ni * 8 + tg * 2;
                            *(float2*)(dst + cn) = make_float2(acc[mi][ni][half * 2],
                                                               acc[mi][ni][half * 2 + 1]);
                        }
                    }
            } else {
                const int Wf = jb.Wc * jb.F;
                const int HWf = jb.Hc * jb.F * Wf;
                const int b = rm / HWf;
                const int rem = rm - b * HWf;
                const int h = rem / Wf;
                const int w = rem - h * Wf;
                const int crow = (b * jb.Hc + h / jb.F) * jb.Wc + (w / jb.F);
                const float* csrc = jb.Cadd + (size_t)crow * 256;
                float* dst = jb.out + (size_t)rm * 256;
#pragma unroll
                for (int ni = 0; ni < 4; ++ni) {
                    const int cn = n0 + wn * 32 + ni * 8 + tg * 2;
                    float2 cv = *(const float2*)(csrc + cn);
                    *(float2*)(dst + cn) = make_float2(acc[mi][ni][half * 2] + cv.x,
                                                       acc[mi][ni][half * 2 + 1] + cv.y);
                }
            }
        }
    }

    // Producers: make C visible, then signal.
    if (jb.dep == 1) {
        __threadfence();
        __syncthreads();
        if (tid == 0) atomicAdd(&g_done, 1);
    }
}

// ---------------------------------------------------------------------------
// Launch
// ---------------------------------------------------------------------------
extern "C" void kernel_launch(void* const* d_in, const int* in_sizes, int n_in,
                              void* d_out, int out_size) {
    (void)n_in; (void)out_size;

    const float* x0 = (const float*)d_in[0];   // [8,16,16,256]
    const float* x1 = (const float*)d_in[1];   // [8,32,32,256]
    const float* x2 = (const float*)d_in[2];   // [8,64,64,256]

    // setup_inputs() builds the dict INTERLEAVED (qpeer_w0, kvpeer_w0, ...).
    const bool inter = (in_sizes[4] == 2 * 256 * 256);
    const float* kvpeer0 = (const float*)d_in[inter ? 4  : 6];
    const float* kvpeer1 = (const float*)d_in[inter ? 6  : 7];
    const float* kvpeer2 = (const float*)d_in[inter ? 8  : 8];
    const float* kvpar1  = (const float*)d_in[inter ? 10 : 11];
    const float* kvpar2  = (const float*)d_in[inter ? 12 : 12];
    const float* kvkid0  = (const float*)d_in[inter ? 14 : 15];
    const float* kvkid1  = (const float*)d_in[inter ? 16 : 16];

    __half *P0, *Pa, *Pb, *W;
    float *C0, *C1;
    cudaGetSymbolAddress((void**)&P0, g_P0);
    cudaGetSymbolAddress((void**)&Pa, g_Pa);
    cudaGetSymbolAddress((void**)&Pb, g_Pb);
    cudaGetSymbolAddress((void**)&W, g_W);
    cudaGetSymbolAddress((void**)&C0, g_C0);
    cudaGetSymbolAddress((void**)&C1, g_C1);

    float* out0 = (float*)d_out;                 // 8*16*16*256
    float* out1 = out0 + 8 * 16 * 16 * 256;      // 8*32*32*256
    float* out2 = out1 + 8 * 32 * 32 * 256;      // 8*64*64*256

    cudaFuncSetAttribute(gemm_tc, cudaFuncAttributeMaxDynamicSharedMemorySize, SMEM_TOTAL);

    // 1) prep (also resets g_done)
    PrepArgs pa;
    pa.x0 = x0; pa.x1 = x1; pa.x2 = x2;
    pa.w[0] = kvpeer0; pa.w[1] = kvpeer1; pa.w[2] = kvpeer2;
    pa.w[3] = kvpar1;  pa.w[4] = kvpar2;  pa.w[5] = kvkid0;  pa.w[6] = kvkid1;
    prep_kernel<<<(PREP_TOTAL + 255) / 256, 256>>>(pa);

    __half* W0 = W;             // peer0
    __half* W1 = W + 65536;     // peer1
    __half* W2 = W + 131072;    // peer2
    __half* W3 = W + 196608;    // par1
    __half* W4 = W + 262144;    // par2
    __half* W5 = W + 327680;    // kid0
    __half* W6 = W + 393216;    // kid1

    // 2) single merged GEMM launch (producers first: blocks 0..33)
    TCJobs tj;
    tj.njobs = 5;
    tj.nprod = 34;
    //        A1  W1  W2      A2f  out   Cadd    aplane    end  Hc  Wc F  mode dep
    tj.j[0] = { P0, W0, nullptr, nullptr, C0,   nullptr, 128 * 64,  2,   0,  0, 0, 0, 1 };
    tj.j[1] = { Pa, W1, W3,      x0,      C1,   nullptr, 2048 * 64, 34,  0,  0, 0, 0, 1 };
    tj.j[2] = { Pb, W2, W4,      x1,      out2, nullptr, 8192 * 64, 162, 32, 32, 2, 1, 0 };
    tj.j[3] = { Pa, W5, nullptr, nullptr, out0, C0,      2048 * 64, 194, 4,  4,  4, 2, 2 };
    tj.j[4] = { Pb, W6, nullptr, nullptr, out1, C1,      8192 * 64, 322, 16, 16, 2, 2, 2 };
    gemm_tc<<<322, 256, SMEM_TOTAL>>>(tj);
}